// round 3
// baseline (speedup 1.0000x reference)
#include <cuda_runtime.h>
#include <cstdint>
#include <cstddef>

#define XD   512
#define HID_ 1024
#define BB   64
#define TT   512
#define G4   4096
#define MROWS 32768   // BB*TT

typedef unsigned long long u64;

// ---------------- device scratch (static: no allocations allowed) ----------------
__device__ float g_Wx4[(size_t)XD * G4];          //   8 MB packed [k][g*H+j]
__device__ float g_Wh4[(size_t)HID_ * G4];        //  16 MB packed
__device__ float g_b4[G4];
__device__ float g_xproj[(size_t)MROWS * G4];     // 512 MB : X @ Wx (no bias)
__device__ float g_h[2 * HID_ * BB + 64];         // transposed h [col][b], dbl-buffered (+pad: safe over-read)
__device__ unsigned g_bar_cnt;                    // zero-initialized; self-resetting barrier
__device__ volatile unsigned g_bar_phase;

// ---------------- packed fp32 helpers ----------------
__device__ __forceinline__ u64 splat2(float x) {
    u64 r; asm("mov.b64 %0, {%1, %1};" : "=l"(r) : "f"(x)); return r;
}
__device__ __forceinline__ void ffma2(u64& d, u64 a, u64 b) {
    asm("fma.rn.f32x2 %0, %1, %2, %0;" : "+l"(d) : "l"(a), "l"(b));
}
__device__ __forceinline__ float sigmoidf_(float x) { return 1.f / (1.f + __expf(-x)); }

// ---------------- kernel 0: pack weights gate-major ----------------
__global__ void pack_kernel(const float* __restrict__ Wxi, const float* __restrict__ Wxf,
                            const float* __restrict__ Wxo, const float* __restrict__ Wxz,
                            const float* __restrict__ Whi, const float* __restrict__ Whf,
                            const float* __restrict__ Who, const float* __restrict__ Whz,
                            const float* __restrict__ bi,  const float* __restrict__ bf,
                            const float* __restrict__ bo,  const float* __restrict__ bz) {
    int tid0 = blockIdx.x * blockDim.x + threadIdx.x;
    int stride = gridDim.x * blockDim.x;
    for (int idx = tid0; idx < XD * G4; idx += stride) {
        int k = idx >> 12, col = idx & 4095, g = col >> 10, j = col & 1023;
        const float* W = (g == 0) ? Wxi : (g == 1) ? Wxf : (g == 2) ? Wxo : Wxz;
        g_Wx4[idx] = W[k * HID_ + j];
    }
    for (int idx = tid0; idx < HID_ * G4; idx += stride) {
        int k = idx >> 12, col = idx & 4095, g = col >> 10, j = col & 1023;
        const float* W = (g == 0) ? Whi : (g == 1) ? Whf : (g == 2) ? Who : Whz;
        g_Wh4[idx] = W[k * HID_ + j];
    }
    for (int idx = tid0; idx < G4; idx += stride) {
        int g = idx >> 10, j = idx & 1023;
        const float* b = (g == 0) ? bi : (g == 1) ? bf : (g == 2) ? bo : bz;
        g_b4[idx] = b[j];
    }
}

// ---------------- kernel A: xproj = X @ Wx4  (128x128 tile SGEMM, f32x2, pipelined) ----------------
__global__ __launch_bounds__(256) void xproj_kernel(const float* __restrict__ X) {
    __shared__ __align__(16) float As[16][128];   // [k][m] (transposed)
    __shared__ __align__(16) float Bs[16][128];   // [k][n]
    int tid = threadIdx.x;
    int mbase = blockIdx.y * 128;
    int nbase = blockIdx.x * 128;
    int tm = tid >> 4, tn = tid & 15;
    int m0 = tm * 8, n0 = tn * 8;

    // per-thread staging indices for tile loads
    int a_m[2], a_kq[2], b_k[2], b_n[2];
#pragma unroll
    for (int r = 0; r < 2; r++) {
        int idx = tid + r * 256;
        a_m[r] = idx >> 2; a_kq[r] = (idx & 3) * 4;
        b_k[r] = idx >> 5; b_n[r] = (idx & 31) * 4;
    }

    u64 acc[8][4];
#pragma unroll
    for (int i = 0; i < 8; i++)
#pragma unroll
        for (int j = 0; j < 4; j++) acc[i][j] = 0ULL;

    float4 a_reg[2], b_reg[2];
    // prologue: load tile 0
#pragma unroll
    for (int r = 0; r < 2; r++) {
        a_reg[r] = *(const float4*)&X[(size_t)(mbase + a_m[r]) * XD + 0 + a_kq[r]];
        b_reg[r] = *(const float4*)&g_Wx4[(size_t)(0 + b_k[r]) * G4 + nbase + b_n[r]];
    }

    for (int k0 = 0; k0 < XD; k0 += 16) {
        // stage current tile into SMEM
#pragma unroll
        for (int r = 0; r < 2; r++) {
            As[a_kq[r] + 0][a_m[r]] = a_reg[r].x;
            As[a_kq[r] + 1][a_m[r]] = a_reg[r].y;
            As[a_kq[r] + 2][a_m[r]] = a_reg[r].z;
            As[a_kq[r] + 3][a_m[r]] = a_reg[r].w;
            *(float4*)&Bs[b_k[r]][b_n[r]] = b_reg[r];
        }
        __syncthreads();
        // prefetch next tile (overlaps with compute below)
        if (k0 + 16 < XD) {
#pragma unroll
            for (int r = 0; r < 2; r++) {
                a_reg[r] = *(const float4*)&X[(size_t)(mbase + a_m[r]) * XD + (k0 + 16) + a_kq[r]];
                b_reg[r] = *(const float4*)&g_Wx4[(size_t)(k0 + 16 + b_k[r]) * G4 + nbase + b_n[r]];
            }
        }
#pragma unroll
        for (int kk = 0; kk < 16; kk++) {
            float4 a0 = *(const float4*)&As[kk][m0];
            float4 a1 = *(const float4*)&As[kk][m0 + 4];
            ulonglong2 b01 = *(const ulonglong2*)&Bs[kk][n0];
            ulonglong2 b23 = *(const ulonglong2*)&Bs[kk][n0 + 4];
            float am[8] = {a0.x, a0.y, a0.z, a0.w, a1.x, a1.y, a1.z, a1.w};
#pragma unroll
            for (int i = 0; i < 8; i++) {
                u64 aa = splat2(am[i]);
                ffma2(acc[i][0], aa, b01.x);
                ffma2(acc[i][1], aa, b01.y);
                ffma2(acc[i][2], aa, b23.x);
                ffma2(acc[i][3], aa, b23.y);
            }
        }
        __syncthreads();
    }
#pragma unroll
    for (int i = 0; i < 8; i++) {
        size_t off = (size_t)(mbase + m0 + i) * G4 + nbase + n0;
        ulonglong2 s0; s0.x = acc[i][0]; s0.y = acc[i][1];
        ulonglong2 s1; s1.x = acc[i][2]; s1.y = acc[i][3];
        *(ulonglong2*)&g_xproj[off]     = s0;
        *(ulonglong2*)&g_xproj[off + 4] = s1;
    }
}

// ---------------- kernel B: persistent recurrence ----------------
#define NCTA 128
#define NC   8                 // h-cols per CTA -> 32 gate cols -> 16 packed pairs
#define NPC  16
#define PROW 40                // padded partial row (floats)
#define THR  512
#define SMEM_BYTES (HID_ * NPC * 8 + 8 * BB * PROW * 4 + 32 * 4)

__device__ __forceinline__ void grid_sync(unsigned& phase) {
    __threadfence();
    __syncthreads();
    if (threadIdx.x == 0) {
        unsigned arrived = atomicAdd(&g_bar_cnt, 1u) + 1u;
        if (arrived == gridDim.x) {
            g_bar_cnt = 0;           // self-reset before release
            __threadfence();
            g_bar_phase = phase + 1u;
        } else {
            while (g_bar_phase == phase) { }
        }
        phase = phase + 1u;
        __threadfence();
    }
    __syncthreads();
}

__global__ __launch_bounds__(THR, 1) void lstm_kernel(float* __restrict__ out) {
    extern __shared__ __align__(16) char smem_raw[];
    u64*   Ws     = (u64*)smem_raw;                       // [1024][16] f32x2 pairs
    float* part   = (float*)(smem_raw + HID_ * NPC * 8);  // [8][64][PROW]
    float* bias_s = part + 8 * BB * PROW;                 // [32]

    int tid = threadIdx.x;
    int j0  = blockIdx.x * NC;

    // Load Wh slice into SMEM (once): pc = g*4+pp -> cols (g*1024 + j0 + 2pp, +1)
    for (int idx = tid; idx < HID_ * NPC; idx += THR) {
        int k = idx >> 4, pc = idx & 15;
        int g = pc >> 2, pp = pc & 3;
        float2 v = *(const float2*)&g_Wh4[(size_t)k * G4 + g * HID_ + j0 + pp * 2];
        Ws[idx] = reinterpret_cast<const u64&>(v);
    }
    if (tid < 32) {
        int g = tid >> 3, j = tid & 7;
        bias_s[tid] = g_b4[g * HID_ + j0 + j];
    }
    // zero our slice of h buffer 0
    if (tid < NC * BB)
        g_h[(j0 + (tid >> 6)) * BB + (tid & 63)] = 0.f;

    unsigned phase = 0;
    if (tid == 0) phase = g_bar_phase;   // resume phase across graph replays

    // GEMM-role decomposition: 8 k-slices x (16 b-groups x 4 pc-groups)
    int ks = tid >> 6;
    int s  = tid & 63;
    int bg = s >> 2;
    int pg = s & 3;
    int b0 = bg * 4;
    int pc0 = pg * 4;
    int kbase = ks * 128;

    // activation-role decomposition: 1 output per thread (b = tid>>3, j = tid&7)
    int p_b = tid >> 3;          // 0..63
    int p_j = tid & 7;
    float c = 0.f;

    grid_sync(phase);            // h zeros visible everywhere

    // prefetch xproj for step 0
    float xp[4], xpn[4];
#pragma unroll
    for (int g = 0; g < 4; g++)
        xp[g] = g_xproj[(size_t)(p_b * TT + 0) * G4 + g * HID_ + j0 + p_j];

    for (int t = 0; t < TT; t++) {
        const float* hprev = g_h + (t & 1) * (HID_ * BB);
        float* hnext = g_h + ((t + 1) & 1) * (HID_ * BB);

        u64 acc[4][4];
#pragma unroll
        for (int i = 0; i < 4; i++)
#pragma unroll
            for (int j = 0; j < 4; j++) acc[i][j] = 0ULL;

        const float* hrow = hprev + kbase * BB + b0;
        const u64*   wrow = Ws + kbase * NPC + pc0;
#pragma unroll 8
        for (int kk = 0; kk < 128; kk++) {
            float4 hv = *(const float4*)(hrow);
            ulonglong2 w01 = *(const ulonglong2*)(wrow);
            ulonglong2 w23 = *(const ulonglong2*)(wrow + 2);
            float hm[4] = {hv.x, hv.y, hv.z, hv.w};
#pragma unroll
            for (int i = 0; i < 4; i++) {
                u64 aa = splat2(hm[i]);
                ffma2(acc[i][0], aa, w01.x);
                ffma2(acc[i][1], aa, w01.y);
                ffma2(acc[i][2], aa, w23.x);
                ffma2(acc[i][3], aa, w23.y);
            }
            hrow += BB;
            wrow += NPC;
        }
        // write partials: row = (ks, b), gc = pg*8 .. pg*8+7
#pragma unroll
        for (int i = 0; i < 4; i++) {
            float* dst = part + (size_t)(ks * BB + b0 + i) * PROW + pc0 * 2;
            ulonglong2 s0; s0.x = acc[i][0]; s0.y = acc[i][1];
            ulonglong2 s1; s1.x = acc[i][2]; s1.y = acc[i][3];
            *(ulonglong2*)dst       = s0;
            *(ulonglong2*)(dst + 4) = s1;
        }

        // issue next-step xproj loads (h-independent; hides DRAM latency)
        if (t + 1 < TT) {
#pragma unroll
            for (int g = 0; g < 4; g++)
                xpn[g] = g_xproj[(size_t)(p_b * TT + (t + 1)) * G4 + g * HID_ + j0 + p_j];
        }
        __syncthreads();

        // activation phase: one (b, j) output per thread
        float ga[4];
#pragma unroll
        for (int g = 0; g < 4; g++) {
            float sa = xp[g] + bias_s[g * 8 + p_j];
#pragma unroll
            for (int sck = 0; sck < 8; sck++)
                sa += part[(size_t)(sck * BB + p_b) * PROW + g * 8 + p_j];
            ga[g] = sa;
        }
        {
            float ig = sigmoidf_(ga[0]), fg = sigmoidf_(ga[1]);
            float og = sigmoidf_(ga[2]), zg = tanhf(ga[3]);
            c = ig * zg + fg * c;
            float hv = og * tanhf(c);
            hnext[(j0 + p_j) * BB + p_b] = hv;
            out[((size_t)p_b * TT + t) * HID_ + j0 + p_j] = hv;
        }
#pragma unroll
        for (int g = 0; g < 4; g++) xp[g] = xpn[g];

        if (t + 1 < TT) grid_sync(phase);
    }
}

// ---------------- launch ----------------
extern "C" void kernel_launch(void* const* d_in, const int* in_sizes, int n_in,
                              void* d_out, int out_size) {
    const float* X   = (const float*)d_in[0];
    const float* Whi = (const float*)d_in[1];
    const float* Wxi = (const float*)d_in[2];
    const float* bi  = (const float*)d_in[3];
    const float* Whf = (const float*)d_in[4];
    const float* Wxf = (const float*)d_in[5];
    const float* bf  = (const float*)d_in[6];
    const float* Who = (const float*)d_in[7];
    const float* Wxo = (const float*)d_in[8];
    const float* bo  = (const float*)d_in[9];
    const float* Whz = (const float*)d_in[10];
    const float* Wxz = (const float*)d_in[11];
    const float* bz  = (const float*)d_in[12];

    pack_kernel<<<1024, 256>>>(Wxi, Wxf, Wxo, Wxz, Whi, Whf, Who, Whz, bi, bf, bo, bz);

    dim3 gA(32, 256);   // N tiles x M tiles
    xproj_kernel<<<gA, 256>>>(X);

    cudaFuncSetAttribute(lstm_kernel, cudaFuncAttributeMaxDynamicSharedMemorySize, SMEM_BYTES);
    lstm_kernel<<<NCTA, THR, SMEM_BYTES>>>((float*)d_out);
}

// round 5
// speedup vs baseline: 1.2742x; 1.2742x over previous
#include <cuda_runtime.h>
#include <cuda_bf16.h>
#include <cstdint>
#include <cstddef>

#define XD   512
#define HID_ 1024
#define BB   64
#define TT   512
#define G4   4096
#define MROWS 32768
#define NCTA 128
#define THR  256

typedef unsigned long long u64;
typedef unsigned int u32;

// ---------------- device scratch ----------------
__device__ float g_Wx4[(size_t)XD * G4];
__device__ float g_Wh4[(size_t)HID_ * G4];
__device__ float g_b4[G4];
__device__ float g_xproj[(size_t)MROWS * G4];                       // X@Wx + bias
__device__ __align__(16) __nv_bfloat16 g_hbf[2][2][BB][HID_];       // [parity][hi/lo][b][k]
__device__ unsigned g_bar_cnt;
__device__ volatile unsigned g_bar_phase;

// ---------------- helpers ----------------
#define SW128(x) ((x) ^ (((x) >> 3) & 0x70))

__device__ __forceinline__ u32 smem_u32(const void* p) {
    u32 a; asm("{ .reg .u64 t; cvta.to.shared.u64 t, %1; cvt.u32.u64 %0, t; }" : "=r"(a) : "l"(p));
    return a;
}
__device__ __forceinline__ void ldsm4(u32& r0, u32& r1, u32& r2, u32& r3, u32 addr) {
    asm volatile("ldmatrix.sync.aligned.m8n8.x4.shared.b16 {%0,%1,%2,%3}, [%4];"
                 : "=r"(r0), "=r"(r1), "=r"(r2), "=r"(r3) : "r"(addr));
}
__device__ __forceinline__ void mma16816(float* c, u32 a0, u32 a1, u32 a2, u32 a3, u32 b0, u32 b1) {
    asm volatile("mma.sync.aligned.m16n8k16.row.col.f32.bf16.bf16.f32 "
                 "{%0,%1,%2,%3}, {%4,%5,%6,%7}, {%8,%9}, {%0,%1,%2,%3};"
                 : "+f"(c[0]), "+f"(c[1]), "+f"(c[2]), "+f"(c[3])
                 : "r"(a0), "r"(a1), "r"(a2), "r"(a3), "r"(b0), "r"(b1));
}
__device__ __forceinline__ u64 splat2(float x) {
    u64 r; asm("mov.b64 %0, {%1, %1};" : "=l"(r) : "f"(x)); return r;
}
__device__ __forceinline__ void ffma2(u64& d, u64 a, u64 b) {
    asm("fma.rn.f32x2 %0, %1, %2, %0;" : "+l"(d) : "l"(a), "l"(b));
}
__device__ __forceinline__ float sigmoidf_(float x) { return 1.f / (1.f + __expf(-x)); }

// ---------------- kernel 0: pack weights gate-major ----------------
__global__ void pack_kernel(const float* __restrict__ Wxi, const float* __restrict__ Wxf,
                            const float* __restrict__ Wxo, const float* __restrict__ Wxz,
                            const float* __restrict__ Whi, const float* __restrict__ Whf,
                            const float* __restrict__ Who, const float* __restrict__ Whz,
                            const float* __restrict__ bi,  const float* __restrict__ bf,
                            const float* __restrict__ bo,  const float* __restrict__ bz) {
    int tid0 = blockIdx.x * blockDim.x + threadIdx.x;
    int stride = gridDim.x * blockDim.x;
    for (int idx = tid0; idx < XD * G4; idx += stride) {
        int k = idx >> 12, col = idx & 4095, g = col >> 10, j = col & 1023;
        const float* W = (g == 0) ? Wxi : (g == 1) ? Wxf : (g == 2) ? Wxo : Wxz;
        g_Wx4[idx] = W[k * HID_ + j];
    }
    for (int idx = tid0; idx < HID_ * G4; idx += stride) {
        int k = idx >> 12, col = idx & 4095, g = col >> 10, j = col & 1023;
        const float* W = (g == 0) ? Whi : (g == 1) ? Whf : (g == 2) ? Who : Whz;
        g_Wh4[idx] = W[k * HID_ + j];
    }
    for (int idx = tid0; idx < G4; idx += stride) {
        int g = idx >> 10, j = idx & 1023;
        const float* b = (g == 0) ? bi : (g == 1) ? bf : (g == 2) ? bo : bz;
        g_b4[idx] = b[j];
    }
}

// ---------------- kernel A: xproj = X @ Wx4 + b  (fp32 f32x2 SGEMM) ----------------
__global__ __launch_bounds__(256) void xproj_kernel(const float* __restrict__ X) {
    __shared__ __align__(16) float As[16][128];
    __shared__ __align__(16) float Bs[16][128];
    int tid = threadIdx.x;
    int mbase = blockIdx.y * 128;
    int nbase = blockIdx.x * 128;
    int tm = tid >> 4, tn = tid & 15;
    int m0 = tm * 8, n0 = tn * 8;

    int a_m[2], a_kq[2], b_k[2], b_n[2];
#pragma unroll
    for (int r = 0; r < 2; r++) {
        int idx = tid + r * 256;
        a_m[r] = idx >> 2; a_kq[r] = (idx & 3) * 4;
        b_k[r] = idx >> 5; b_n[r] = (idx & 31) * 4;
    }

    u64 acc[8][4];
#pragma unroll
    for (int i = 0; i < 8; i++)
#pragma unroll
        for (int j = 0; j < 4; j++) acc[i][j] = 0ULL;

    float4 a_reg[2], b_reg[2];
#pragma unroll
    for (int r = 0; r < 2; r++) {
        a_reg[r] = *(const float4*)&X[(size_t)(mbase + a_m[r]) * XD + a_kq[r]];
        b_reg[r] = *(const float4*)&g_Wx4[(size_t)b_k[r] * G4 + nbase + b_n[r]];
    }

    for (int k0 = 0; k0 < XD; k0 += 16) {
#pragma unroll
        for (int r = 0; r < 2; r++) {
            As[a_kq[r] + 0][a_m[r]] = a_reg[r].x;
            As[a_kq[r] + 1][a_m[r]] = a_reg[r].y;
            As[a_kq[r] + 2][a_m[r]] = a_reg[r].z;
            As[a_kq[r] + 3][a_m[r]] = a_reg[r].w;
            *(float4*)&Bs[b_k[r]][b_n[r]] = b_reg[r];
        }
        __syncthreads();
        if (k0 + 16 < XD) {
#pragma unroll
            for (int r = 0; r < 2; r++) {
                a_reg[r] = *(const float4*)&X[(size_t)(mbase + a_m[r]) * XD + (k0 + 16) + a_kq[r]];
                b_reg[r] = *(const float4*)&g_Wx4[(size_t)(k0 + 16 + b_k[r]) * G4 + nbase + b_n[r]];
            }
        }
#pragma unroll
        for (int kk = 0; kk < 16; kk++) {
            float4 a0 = *(const float4*)&As[kk][m0];
            float4 a1 = *(const float4*)&As[kk][m0 + 4];
            ulonglong2 b01 = *(const ulonglong2*)&Bs[kk][n0];
            ulonglong2 b23 = *(const ulonglong2*)&Bs[kk][n0 + 4];
            float am[8] = {a0.x, a0.y, a0.z, a0.w, a1.x, a1.y, a1.z, a1.w};
#pragma unroll
            for (int i = 0; i < 8; i++) {
                u64 aa = splat2(am[i]);
                ffma2(acc[i][0], aa, b01.x);
                ffma2(acc[i][1], aa, b01.y);
                ffma2(acc[i][2], aa, b23.x);
                ffma2(acc[i][3], aa, b23.y);
            }
        }
        __syncthreads();
    }
    float bsv[8];
#pragma unroll
    for (int j = 0; j < 8; j++) bsv[j] = g_b4[nbase + n0 + j];
#pragma unroll
    for (int i = 0; i < 8; i++) {
        float r[8];
#pragma unroll
        for (int j = 0; j < 4; j++) {
            float2 v = *(float2*)&acc[i][j];
            r[2 * j] = v.x + bsv[2 * j];
            r[2 * j + 1] = v.y + bsv[2 * j + 1];
        }
        size_t off = (size_t)(mbase + m0 + i) * G4 + nbase + n0;
        *(float4*)&g_xproj[off]     = make_float4(r[0], r[1], r[2], r[3]);
        *(float4*)&g_xproj[off + 4] = make_float4(r[4], r[5], r[6], r[7]);
    }
}

// ---------------- kernel B: persistent HMMA recurrence ----------------
// SMEM: [0,64K) Wh hi | [64K,128K) Wh lo | [128K,144K) A hi | [144K,160K) A lo | [160K, +8.5K) gate sums
#define WHI_OFF   0
#define WLO_OFF   65536
#define ABUF_HI   131072
#define ABUF_LO   147456
#define GSUM_OFF  163840
#define GROW      34
#define SMEM_BYTES (GSUM_OFF + BB * GROW * 4)

__device__ __forceinline__ void grid_sync(unsigned& phase) {
    __threadfence();
    __syncthreads();
    if (threadIdx.x == 0) {
        unsigned arrived = atomicAdd(&g_bar_cnt, 1u) + 1u;
        if (arrived == gridDim.x) {
            g_bar_cnt = 0;
            __threadfence();
            g_bar_phase = phase + 1u;
        } else {
            while (g_bar_phase == phase) { }
        }
        phase = phase + 1u;
        __threadfence();
    }
    __syncthreads();
}

__global__ __launch_bounds__(THR, 1) void lstm_kernel(float* __restrict__ out) {
    extern __shared__ __align__(1024) char sm[];
    u32 smem_base = smem_u32(sm);
    float* gsum = (float*)(sm + GSUM_OFF);
    int tid = threadIdx.x;
    int lane = tid & 31, wid = tid >> 5;
    int mt = wid & 3, nh = wid >> 2;
    int j0 = blockIdx.x * 8;

    // ---- fill Wh slice hi/lo into SMEM atoms (8rows x 64cols, SW128) ----
    for (int idx = tid; idx < 32 * 1024; idx += THR) {
        int n = idx & 31, k = idx >> 5;
        int gc = (n >> 3) * 1024 + j0 + (n & 7);
        float wv = g_Wh4[(size_t)k * G4 + gc];
        __nv_bfloat16 hi = __float2bfloat16(wv);
        __nv_bfloat16 lo = __float2bfloat16(wv - __bfloat162float(hi));
        u32 off = (u32)((n >> 3) + ((k >> 6) << 2)) * 1024u
                + (u32)SW128(((n & 7) << 7) + ((k & 63) << 1));
        *(__nv_bfloat16*)(sm + WHI_OFF + off) = hi;
        *(__nv_bfloat16*)(sm + WLO_OFF + off) = lo;
    }

    // ---- activation ownership: (b, jp pair) ----
    int ab = tid >> 2;
    int ajp = (tid & 3) * 2;
    *(u32*)&g_hbf[0][0][ab][j0 + ajp] = 0u;     // zero h image parity 0
    *(u32*)&g_hbf[0][1][ab][j0 + ajp] = 0u;
    float c0s = 0.f, c1s = 0.f;

    // ---- chunk loader precompute ----
    int ld_row[4]; int ld_kloc[4]; u32 sts_off[4];
#pragma unroll
    for (int q = 0; q < 4; q++) {
        int idx = q * 256 + tid;
        int b = idx >> 4, u = idx & 15, kloc = u * 8;
        ld_row[q] = b; ld_kloc[q] = kloc;
        sts_off[q] = (u32)((b >> 3) + ((kloc >> 6) << 3)) * 1024u
                   + (u32)SW128(((b & 7) << 7) + ((kloc & 63) << 1));
    }

    // ---- mma fragment address components ----
    int arow = mt * 16 + (lane & 7) + (lane & 8);          // batch row for A mats
    u32 a_inner = (u32)((arow & 7) << 7);
    int aAtomR = arow >> 3;
    int kbitA = (lane & 16) ? 8 : 0;
    int nrow = nh * 16 + (lane & 7) + ((lane & 16) ? 8 : 0);  // n row for B mats
    u32 b_inner = (u32)((nrow & 7) << 7);
    int bAtomN = nrow >> 3;
    int kbitB = (lane & 8);

    unsigned phase = 0;
    if (tid == 0) phase = g_bar_phase;
    grid_sync(phase);                                       // Wh + h zeros visible

    for (int t = 0; t < TT; t++) {
        int par = t & 1, npn = par ^ 1;
        const __nv_bfloat16* hhi = &g_hbf[par][0][0][0];
        const __nv_bfloat16* hlo = &g_hbf[par][1][0][0];

        // xproj prefetch for this step
        float2 xpv[4];
        {
            size_t xb = ((size_t)ab * TT + t) * G4 + j0 + ajp;
#pragma unroll
            for (int g = 0; g < 4; g++)
                xpv[g] = *(const float2*)&g_xproj[xb + (size_t)g * 1024];
        }

        // prefetch chunk 0
        uint4 rh[4], rl[4];
#pragma unroll
        for (int q = 0; q < 4; q++) {
            rh[q] = *(const uint4*)&hhi[ld_row[q] * 1024 + ld_kloc[q]];
            rl[q] = *(const uint4*)&hlo[ld_row[q] * 1024 + ld_kloc[q]];
        }

        float acc[8];
#pragma unroll
        for (int i = 0; i < 8; i++) acc[i] = 0.f;

#pragma unroll 1
        for (int ck = 0; ck < 8; ck++) {
#pragma unroll
            for (int q = 0; q < 4; q++) {
                *(uint4*)(sm + ABUF_HI + sts_off[q]) = rh[q];
                *(uint4*)(sm + ABUF_LO + sts_off[q]) = rl[q];
            }
            __syncthreads();
            if (ck < 7) {
                int kc = (ck + 1) * 128;
#pragma unroll
                for (int q = 0; q < 4; q++) {
                    rh[q] = *(const uint4*)&hhi[ld_row[q] * 1024 + kc + ld_kloc[q]];
                    rl[q] = *(const uint4*)&hlo[ld_row[q] * 1024 + kc + ld_kloc[q]];
                }
            }
#pragma unroll
            for (int ks = 0; ks < 8; ks++) {
                int klA = ks * 16 + kbitA;
                u32 aoff = (u32)(aAtomR + ((klA >> 6) << 3)) * 1024u
                         + (u32)SW128(a_inner + ((klA & 63) << 1));
                int kB = ck * 128 + ks * 16 + kbitB;
                u32 boff = (u32)(bAtomN + ((kB >> 6) << 2)) * 1024u
                         + (u32)SW128(b_inner + ((kB & 63) << 1));
                u32 ah0, ah1, ah2, ah3, al0, al1, al2, al3;
                u32 bh0, bh1, bh2, bh3, bl0, bl1, bl2, bl3;
                ldsm4(ah0, ah1, ah2, ah3, smem_base + ABUF_HI + aoff);
                ldsm4(al0, al1, al2, al3, smem_base + ABUF_LO + aoff);
                ldsm4(bh0, bh1, bh2, bh3, smem_base + WHI_OFF + boff);
                ldsm4(bl0, bl1, bl2, bl3, smem_base + WLO_OFF + boff);
                mma16816(acc,     ah0, ah1, ah2, ah3, bh0, bh1);
                mma16816(acc,     ah0, ah1, ah2, ah3, bl0, bl1);
                mma16816(acc,     al0, al1, al2, al3, bh0, bh1);
                mma16816(acc + 4, ah0, ah1, ah2, ah3, bh2, bh3);
                mma16816(acc + 4, ah0, ah1, ah2, ah3, bl2, bl3);
                mma16816(acc + 4, al0, al1, al2, al3, bh2, bh3);
            }
            __syncthreads();
        }

        // fragment writeback to gate-sum tile
        {
            int r0 = mt * 16 + (lane >> 2);
            int cb = nh * 16 + (lane & 3) * 2;
            *(float2*)&gsum[r0 * GROW + cb]           = make_float2(acc[0], acc[1]);
            *(float2*)&gsum[(r0 + 8) * GROW + cb]     = make_float2(acc[2], acc[3]);
            *(float2*)&gsum[r0 * GROW + cb + 8]       = make_float2(acc[4], acc[5]);
            *(float2*)&gsum[(r0 + 8) * GROW + cb + 8] = make_float2(acc[6], acc[7]);
        }
        __syncthreads();

        // activation: 2 cells per thread
        {
            float2 vi = *(float2*)&gsum[ab * GROW + 0 + ajp];
            float2 vf = *(float2*)&gsum[ab * GROW + 8 + ajp];
            float2 vo = *(float2*)&gsum[ab * GROW + 16 + ajp];
            float2 vz = *(float2*)&gsum[ab * GROW + 24 + ajp];
            float gi0 = vi.x + xpv[0].x, gi1 = vi.y + xpv[0].y;
            float gf0 = vf.x + xpv[1].x, gf1 = vf.y + xpv[1].y;
            float go0 = vo.x + xpv[2].x, go1 = vo.y + xpv[2].y;
            float gz0 = vz.x + xpv[3].x, gz1 = vz.y + xpv[3].y;
            float i0 = sigmoidf_(gi0), f0 = sigmoidf_(gf0), o0 = sigmoidf_(go0), z0 = tanhf(gz0);
            float i1 = sigmoidf_(gi1), f1 = sigmoidf_(gf1), o1 = sigmoidf_(go1), z1 = tanhf(gz1);
            c0s = i0 * z0 + f0 * c0s;
            c1s = i1 * z1 + f1 * c1s;
            float hv0 = o0 * tanhf(c0s);
            float hv1 = o1 * tanhf(c1s);
            *(float2*)&out[((size_t)ab * TT + t) * HID_ + j0 + ajp] = make_float2(hv0, hv1);
            __nv_bfloat16 h0 = __float2bfloat16(hv0);
            __nv_bfloat16 h1 = __float2bfloat16(hv1);
            __nv_bfloat16 l0 = __float2bfloat16(hv0 - __bfloat162float(h0));
            __nv_bfloat16 l1 = __float2bfloat16(hv1 - __bfloat162float(h1));
            u32 hw = (u32)__bfloat16_as_ushort(h0) | ((u32)__bfloat16_as_ushort(h1) << 16);
            u32 lw = (u32)__bfloat16_as_ushort(l0) | ((u32)__bfloat16_as_ushort(l1) << 16);
            *(u32*)&g_hbf[npn][0][ab][j0 + ajp] = hw;
            *(u32*)&g_hbf[npn][1][ab][j0 + ajp] = lw;
        }

        if (t + 1 < TT) grid_sync(phase);
    }
}

// ---------------- launch ----------------
extern "C" void kernel_launch(void* const* d_in, const int* in_sizes, int n_in,
                              void* d_out, int out_size) {
    const float* X   = (const float*)d_in[0];
    const float* Whi = (const float*)d_in[1];
    const float* Wxi = (const float*)d_in[2];
    const float* bi  = (const float*)d_in[3];
    const float* Whf = (const float*)d_in[4];
    const float* Wxf = (const float*)d_in[5];
    const float* bf  = (const float*)d_in[6];
    const float* Who = (const float*)d_in[7];
    const float* Wxo = (const float*)d_in[8];
    const float* bo  = (const float*)d_in[9];
    const float* Whz = (const float*)d_in[10];
    const float* Wxz = (const float*)d_in[11];
    const float* bz  = (const float*)d_in[12];

    pack_kernel<<<1024, 256>>>(Wxi, Wxf, Wxo, Wxz, Whi, Whf, Who, Whz, bi, bf, bo, bz);

    dim3 gA(32, 256);
    xproj_kernel<<<gA, 256>>>(X);

    cudaFuncSetAttribute(lstm_kernel, cudaFuncAttributeMaxDynamicSharedMemorySize, SMEM_BYTES);
    lstm_kernel<<<NCTA, THR, SMEM_BYTES>>>((float*)d_out);
}

// round 6
// speedup vs baseline: 1.6659x; 1.3074x over previous
#include <cuda_runtime.h>
#include <cuda_bf16.h>
#include <cstdint>
#include <cstddef>

#define XD   512
#define HID_ 1024
#define BB   64
#define TT   512
#define G4   4096
#define MROWS 32768
#define NCTA 128
#define THR  256

typedef unsigned long long u64;
typedef unsigned int u32;

// ---------------- device scratch ----------------
__device__ float g_Wh4[(size_t)HID_ * G4];
__device__ float g_b4[G4];
__device__ float g_xproj[(size_t)MROWS * G4];                       // X@Wx + bias
__device__ __align__(16) __nv_bfloat16 g_hbf[2][2][BB][HID_];       // [parity][hi/lo][b][k]
// bf16 hi/lo images in SW128 blocked-atom layout (16KB regions per (tile, kchunk))
__device__ __align__(16) __nv_bfloat16 g_XH[(size_t)MROWS * XD];
__device__ __align__(16) __nv_bfloat16 g_XL[(size_t)MROWS * XD];
__device__ __align__(16) __nv_bfloat16 g_WXH[(size_t)G4 * XD];
__device__ __align__(16) __nv_bfloat16 g_WXL[(size_t)G4 * XD];
__device__ unsigned g_bar_cnt;
__device__ volatile unsigned g_bar_phase;

// ---------------- helpers ----------------
#define SW128(x) ((x) ^ (((x) >> 3) & 0x70))

__device__ __forceinline__ u32 smem_u32(const void* p) {
    u32 a; asm("{ .reg .u64 t; cvta.to.shared.u64 t, %1; cvt.u32.u64 %0, t; }" : "=r"(a) : "l"(p));
    return a;
}
__device__ __forceinline__ void ldsm4(u32& r0, u32& r1, u32& r2, u32& r3, u32 addr) {
    asm volatile("ldmatrix.sync.aligned.m8n8.x4.shared.b16 {%0,%1,%2,%3}, [%4];"
                 : "=r"(r0), "=r"(r1), "=r"(r2), "=r"(r3) : "r"(addr));
}
__device__ __forceinline__ void mma16816(float* c, u32 a0, u32 a1, u32 a2, u32 a3, u32 b0, u32 b1) {
    asm volatile("mma.sync.aligned.m16n8k16.row.col.f32.bf16.bf16.f32 "
                 "{%0,%1,%2,%3}, {%4,%5,%6,%7}, {%8,%9}, {%0,%1,%2,%3};"
                 : "+f"(c[0]), "+f"(c[1]), "+f"(c[2]), "+f"(c[3])
                 : "r"(a0), "r"(a1), "r"(a2), "r"(a3), "r"(b0), "r"(b1));
}
__device__ __forceinline__ void cp_async16(u32 dst, const void* src) {
    asm volatile("cp.async.cg.shared.global [%0], [%1], 16;" :: "r"(dst), "l"(src) : "memory");
}
__device__ __forceinline__ void cp_commit() { asm volatile("cp.async.commit_group;" ::: "memory"); }
template<int N> __device__ __forceinline__ void cp_wait() {
    asm volatile("cp.async.wait_group %0;" :: "n"(N) : "memory");
}
__device__ __forceinline__ float sigmoidf_(float x) { return 1.f / (1.f + __expf(-x)); }

// split fp32 -> (hi, lo) bf16
__device__ __forceinline__ void bsplit(float v, __nv_bfloat16& hi, __nv_bfloat16& lo) {
    hi = __float2bfloat16(v);
    lo = __float2bfloat16(v - __bfloat162float(hi));
}

// ---------------- kernel 0: pack Wh gate-major + build bf16 images ----------------
__global__ void pack_kernel(const float* __restrict__ X,
                            const float* __restrict__ Wxi, const float* __restrict__ Wxf,
                            const float* __restrict__ Wxo, const float* __restrict__ Wxz,
                            const float* __restrict__ Whi, const float* __restrict__ Whf,
                            const float* __restrict__ Who, const float* __restrict__ Whz,
                            const float* __restrict__ bi,  const float* __restrict__ bf,
                            const float* __restrict__ bo,  const float* __restrict__ bz) {
    int tid0 = blockIdx.x * blockDim.x + threadIdx.x;
    int stride = gridDim.x * blockDim.x;
    // Wh packed fp32 (recurrence re-splits it into SMEM)
    for (int idx = tid0; idx < HID_ * G4; idx += stride) {
        int k = idx >> 12, col = idx & 4095, g = col >> 10, j = col & 1023;
        const float* W = (g == 0) ? Whi : (g == 1) ? Whf : (g == 2) ? Who : Whz;
        g_Wh4[idx] = W[k * HID_ + j];
    }
    for (int idx = tid0; idx < G4; idx += stride) {
        int g = idx >> 10, j = idx & 1023;
        const float* b = (g == 0) ? bi : (g == 1) ? bf : (g == 2) ? bo : bz;
        g_b4[idx] = b[j];
    }
    // X image: [32768 x 512] fp32 -> hi/lo bf16, blocked atoms per (mt, ck)
    for (int idx = tid0; idx < MROWS * (XD / 4); idx += stride) {
        int m = idx >> 7, kq = (idx & 127) * 4;
        float4 v = *(const float4*)&X[(size_t)m * XD + kq];
        __nv_bfloat16 h[4], l[4];
        bsplit(v.x, h[0], l[0]); bsplit(v.y, h[1], l[1]);
        bsplit(v.z, h[2], l[2]); bsplit(v.w, h[3], l[3]);
        int mt = m >> 7, mloc = m & 127, ck = kq >> 6, kloc = kq & 63;
        size_t off = (size_t)(mt * 8 + ck) * 16384 + (size_t)((mloc >> 3) << 10)
                   + (size_t)SW128(((mloc & 7) << 7) + (kloc << 1));
        *(uint2*)((char*)g_XH + off) = *(uint2*)h;
        *(uint2*)((char*)g_XL + off) = *(uint2*)l;
    }
    // Wx image: gate-major col n=g*1024+j, [4096 x 512] -> hi/lo
    for (int idx = tid0; idx < G4 * (XD / 4); idx += stride) {
        int n = idx >> 7, kq = (idx & 127) * 4;
        int g = n >> 10, j = n & 1023;
        const float* W = (g == 0) ? Wxi : (g == 1) ? Wxf : (g == 2) ? Wxo : Wxz;
        __nv_bfloat16 h[4], l[4];
#pragma unroll
        for (int i = 0; i < 4; i++) bsplit(W[(size_t)(kq + i) * HID_ + j], h[i], l[i]);
        int nt = n >> 7, nloc = n & 127, ck = kq >> 6, kloc = kq & 63;
        size_t off = (size_t)(nt * 8 + ck) * 16384 + (size_t)((nloc >> 3) << 10)
                   + (size_t)SW128(((nloc & 7) << 7) + (kloc << 1));
        *(uint2*)((char*)g_WXH + off) = *(uint2*)h;
        *(uint2*)((char*)g_WXL + off) = *(uint2*)l;
    }
}

// ---------------- kernel A: xproj = X @ Wx + b (HMMA bf16 3-product, cp.async pipeline) ----------------
// smem: 2 stages x 64KB: [XH 16K][XL 16K][WH 16K][WL 16K]
#define XP_SMEM 131072

__global__ __launch_bounds__(512) void xproj_kernel() {
    extern __shared__ __align__(1024) char xs[];
    u32 smem_base = smem_u32(xs);
    int tid = threadIdx.x;
    int lane = tid & 31, wid = tid >> 5;
    int mw = wid & 3, nw = (wid >> 2) & 3;
    int ntb = blockIdx.x, mtb = blockIdx.y;

    int r128 = tid >> 7, lane128 = tid & 127;

    // cp.async stage issue
    auto issue = [&](int ck, int stage) {
        size_t xb = (size_t)(mtb * 8 + ck) * 16384 + (size_t)lane128 * 16;
        size_t wb = (size_t)(ntb * 8 + ck) * 16384 + (size_t)lane128 * 16;
        const char* src = (r128 == 0) ? (const char*)g_XH + xb
                        : (r128 == 1) ? (const char*)g_XL + xb
                        : (r128 == 2) ? (const char*)g_WXH + wb
                                      : (const char*)g_WXL + wb;
        u32 dst = smem_base + stage * 65536 + r128 * 16384 + lane128 * 16;
#pragma unroll
        for (int q = 0; q < 8; q++) cp_async16(dst + q * 2048, src + q * 2048);
        cp_commit();
    };

    float acc[2][4][4];
#pragma unroll
    for (int i = 0; i < 2; i++)
#pragma unroll
        for (int j = 0; j < 4; j++)
#pragma unroll
            for (int q = 0; q < 4; q++) acc[i][j][q] = 0.f;

    issue(0, 0);

    // fragment address components
    int kbA = (lane & 16) ? 8 : 0;
    int kbB = lane & 8;
    int ar0 = mw * 32 + (lane & 15);           // + mt2*16
    int br0 = nw * 32 + (lane & 7) + ((lane & 16) ? 8 : 0);  // + bg*16

    for (int ck = 0; ck < 8; ck++) {
        if (ck < 7) { issue(ck + 1, (ck + 1) & 1); cp_wait<1>(); }
        else cp_wait<0>();
        __syncthreads();
        u32 sb = smem_base + (ck & 1) * 65536;
#pragma unroll
        for (int ks = 0; ks < 4; ks++) {
            int klA = ks * 16 + kbA;
            int klB = ks * 16 + kbB;
            u32 ah[2][4], al[2][4], bh[2][4], bl[2][4];
#pragma unroll
            for (int mt2 = 0; mt2 < 2; mt2++) {
                int ar = ar0 + mt2 * 16;
                u32 aoff = (u32)((ar >> 3) << 10) + (u32)SW128(((ar & 7) << 7) + (klA << 1));
                ldsm4(ah[mt2][0], ah[mt2][1], ah[mt2][2], ah[mt2][3], sb + aoff);
                ldsm4(al[mt2][0], al[mt2][1], al[mt2][2], al[mt2][3], sb + 16384 + aoff);
            }
#pragma unroll
            for (int bg = 0; bg < 2; bg++) {
                int br = br0 + bg * 16;
                u32 boff = (u32)((br >> 3) << 10) + (u32)SW128(((br & 7) << 7) + (klB << 1));
                ldsm4(bh[bg][0], bh[bg][1], bh[bg][2], bh[bg][3], sb + 32768 + boff);
                ldsm4(bl[bg][0], bl[bg][1], bl[bg][2], bl[bg][3], sb + 49152 + boff);
            }
#pragma unroll
            for (int mt2 = 0; mt2 < 2; mt2++)
#pragma unroll
                for (int bg = 0; bg < 2; bg++) {
                    float* c0 = acc[mt2][bg * 2];
                    float* c1 = acc[mt2][bg * 2 + 1];
                    mma16816(c0, ah[mt2][0], ah[mt2][1], ah[mt2][2], ah[mt2][3], bh[bg][0], bh[bg][1]);
                    mma16816(c0, ah[mt2][0], ah[mt2][1], ah[mt2][2], ah[mt2][3], bl[bg][0], bl[bg][1]);
                    mma16816(c0, al[mt2][0], al[mt2][1], al[mt2][2], al[mt2][3], bh[bg][0], bh[bg][1]);
                    mma16816(c1, ah[mt2][0], ah[mt2][1], ah[mt2][2], ah[mt2][3], bh[bg][2], bh[bg][3]);
                    mma16816(c1, ah[mt2][0], ah[mt2][1], ah[mt2][2], ah[mt2][3], bl[bg][2], bl[bg][3]);
                    mma16816(c1, al[mt2][0], al[mt2][1], al[mt2][2], al[mt2][3], bh[bg][2], bh[bg][3]);
                }
        }
        __syncthreads();
    }

    // epilogue: + bias, write fp32
    int rowb = mtb * 128 + mw * 32;
    int colb = ntb * 128 + nw * 32;
    float2 bias[4];
#pragma unroll
    for (int nc = 0; nc < 4; nc++) {
        int col = colb + (nc >> 1) * 16 + (nc & 1) * 8 + (lane & 3) * 2;
        bias[nc] = *(const float2*)&g_b4[col];
    }
#pragma unroll
    for (int mt2 = 0; mt2 < 2; mt2++) {
        int r0 = rowb + mt2 * 16 + (lane >> 2);
#pragma unroll
        for (int nc = 0; nc < 4; nc++) {
            int col = colb + (nc >> 1) * 16 + (nc & 1) * 8 + (lane & 3) * 2;
            *(float2*)&g_xproj[(size_t)r0 * G4 + col] =
                make_float2(acc[mt2][nc][0] + bias[nc].x, acc[mt2][nc][1] + bias[nc].y);
            *(float2*)&g_xproj[(size_t)(r0 + 8) * G4 + col] =
                make_float2(acc[mt2][nc][2] + bias[nc].x, acc[mt2][nc][3] + bias[nc].y);
        }
    }
}

// ---------------- kernel B: persistent HMMA recurrence (unchanged from R5) ----------------
#define WHI_OFF   0
#define WLO_OFF   65536
#define ABUF_HI   131072
#define ABUF_LO   147456
#define GSUM_OFF  163840
#define GROW      34
#define SMEM_BYTES (GSUM_OFF + BB * GROW * 4)

__device__ __forceinline__ void grid_sync(unsigned& phase) {
    __threadfence();
    __syncthreads();
    if (threadIdx.x == 0) {
        unsigned arrived = atomicAdd(&g_bar_cnt, 1u) + 1u;
        if (arrived == gridDim.x) {
            g_bar_cnt = 0;
            __threadfence();
            g_bar_phase = phase + 1u;
        } else {
            while (g_bar_phase == phase) { }
        }
        phase = phase + 1u;
        __threadfence();
    }
    __syncthreads();
}

__global__ __launch_bounds__(THR, 1) void lstm_kernel(float* __restrict__ out) {
    extern __shared__ __align__(1024) char sm[];
    u32 smem_base = smem_u32(sm);
    float* gsum = (float*)(sm + GSUM_OFF);
    int tid = threadIdx.x;
    int lane = tid & 31, wid = tid >> 5;
    int mt = wid & 3, nh = wid >> 2;
    int j0 = blockIdx.x * 8;

    for (int idx = tid; idx < 32 * 1024; idx += THR) {
        int n = idx & 31, k = idx >> 5;
        int gc = (n >> 3) * 1024 + j0 + (n & 7);
        float wv = g_Wh4[(size_t)k * G4 + gc];
        __nv_bfloat16 hi = __float2bfloat16(wv);
        __nv_bfloat16 lo = __float2bfloat16(wv - __bfloat162float(hi));
        u32 off = (u32)((n >> 3) + ((k >> 6) << 2)) * 1024u
                + (u32)SW128(((n & 7) << 7) + ((k & 63) << 1));
        *(__nv_bfloat16*)(sm + WHI_OFF + off) = hi;
        *(__nv_bfloat16*)(sm + WLO_OFF + off) = lo;
    }

    int ab = tid >> 2;
    int ajp = (tid & 3) * 2;
    *(u32*)&g_hbf[0][0][ab][j0 + ajp] = 0u;
    *(u32*)&g_hbf[0][1][ab][j0 + ajp] = 0u;
    float c0s = 0.f, c1s = 0.f;

    int ld_row[4]; int ld_kloc[4]; u32 sts_off[4];
#pragma unroll
    for (int q = 0; q < 4; q++) {
        int idx = q * 256 + tid;
        int b = idx >> 4, u = idx & 15, kloc = u * 8;
        ld_row[q] = b; ld_kloc[q] = kloc;
        sts_off[q] = (u32)((b >> 3) + ((kloc >> 6) << 3)) * 1024u
                   + (u32)SW128(((b & 7) << 7) + ((kloc & 63) << 1));
    }

    int arow = mt * 16 + (lane & 7) + (lane & 8);
    u32 a_inner = (u32)((arow & 7) << 7);
    int aAtomR = arow >> 3;
    int kbitA = (lane & 16) ? 8 : 0;
    int nrow = nh * 16 + (lane & 7) + ((lane & 16) ? 8 : 0);
    u32 b_inner = (u32)((nrow & 7) << 7);
    int bAtomN = nrow >> 3;
    int kbitB = (lane & 8);

    unsigned phase = 0;
    if (tid == 0) phase = g_bar_phase;
    grid_sync(phase);

    for (int t = 0; t < TT; t++) {
        int par = t & 1, npn = par ^ 1;
        const __nv_bfloat16* hhi = &g_hbf[par][0][0][0];
        const __nv_bfloat16* hlo = &g_hbf[par][1][0][0];

        float2 xpv[4];
        {
            size_t xb = ((size_t)ab * TT + t) * G4 + j0 + ajp;
#pragma unroll
            for (int g = 0; g < 4; g++)
                xpv[g] = *(const float2*)&g_xproj[xb + (size_t)g * 1024];
        }

        uint4 rh[4], rl[4];
#pragma unroll
        for (int q = 0; q < 4; q++) {
            rh[q] = *(const uint4*)&hhi[ld_row[q] * 1024 + ld_kloc[q]];
            rl[q] = *(const uint4*)&hlo[ld_row[q] * 1024 + ld_kloc[q]];
        }

        float acc[8];
#pragma unroll
        for (int i = 0; i < 8; i++) acc[i] = 0.f;

#pragma unroll 1
        for (int ck = 0; ck < 8; ck++) {
#pragma unroll
            for (int q = 0; q < 4; q++) {
                *(uint4*)(sm + ABUF_HI + sts_off[q]) = rh[q];
                *(uint4*)(sm + ABUF_LO + sts_off[q]) = rl[q];
            }
            __syncthreads();
            if (ck < 7) {
                int kc = (ck + 1) * 128;
#pragma unroll
                for (int q = 0; q < 4; q++) {
                    rh[q] = *(const uint4*)&hhi[ld_row[q] * 1024 + kc + ld_kloc[q]];
                    rl[q] = *(const uint4*)&hlo[ld_row[q] * 1024 + kc + ld_kloc[q]];
                }
            }
#pragma unroll
            for (int ks = 0; ks < 8; ks++) {
                int klA = ks * 16 + kbitA;
                u32 aoff = (u32)(aAtomR + ((klA >> 6) << 3)) * 1024u
                         + (u32)SW128(a_inner + ((klA & 63) << 1));
                int kB = ck * 128 + ks * 16 + kbitB;
                u32 boff = (u32)(bAtomN + ((kB >> 6) << 2)) * 1024u
                         + (u32)SW128(b_inner + ((kB & 63) << 1));
                u32 ah0, ah1, ah2, ah3, al0, al1, al2, al3;
                u32 bh0, bh1, bh2, bh3, bl0, bl1, bl2, bl3;
                ldsm4(ah0, ah1, ah2, ah3, smem_base + ABUF_HI + aoff);
                ldsm4(al0, al1, al2, al3, smem_base + ABUF_LO + aoff);
                ldsm4(bh0, bh1, bh2, bh3, smem_base + WHI_OFF + boff);
                ldsm4(bl0, bl1, bl2, bl3, smem_base + WLO_OFF + boff);
                mma16816(acc,     ah0, ah1, ah2, ah3, bh0, bh1);
                mma16816(acc,     ah0, ah1, ah2, ah3, bl0, bl1);
                mma16816(acc,     al0, al1, al2, al3, bh0, bh1);
                mma16816(acc + 4, ah0, ah1, ah2, ah3, bh2, bh3);
                mma16816(acc + 4, ah0, ah1, ah2, ah3, bl2, bl3);
                mma16816(acc + 4, al0, al1, al2, al3, bh2, bh3);
            }
            __syncthreads();
        }

        {
            int r0 = mt * 16 + (lane >> 2);
            int cb = nh * 16 + (lane & 3) * 2;
            *(float2*)&gsum[r0 * GROW + cb]           = make_float2(acc[0], acc[1]);
            *(float2*)&gsum[(r0 + 8) * GROW + cb]     = make_float2(acc[2], acc[3]);
            *(float2*)&gsum[r0 * GROW + cb + 8]       = make_float2(acc[4], acc[5]);
            *(float2*)&gsum[(r0 + 8) * GROW + cb + 8] = make_float2(acc[6], acc[7]);
        }
        __syncthreads();

        {
            float2 vi = *(float2*)&gsum[ab * GROW + 0 + ajp];
            float2 vf = *(float2*)&gsum[ab * GROW + 8 + ajp];
            float2 vo = *(float2*)&gsum[ab * GROW + 16 + ajp];
            float2 vz = *(float2*)&gsum[ab * GROW + 24 + ajp];
            float gi0 = vi.x + xpv[0].x, gi1 = vi.y + xpv[0].y;
            float gf0 = vf.x + xpv[1].x, gf1 = vf.y + xpv[1].y;
            float go0 = vo.x + xpv[2].x, go1 = vo.y + xpv[2].y;
            float gz0 = vz.x + xpv[3].x, gz1 = vz.y + xpv[3].y;
            float i0 = sigmoidf_(gi0), f0 = sigmoidf_(gf0), o0 = sigmoidf_(go0), z0 = tanhf(gz0);
            float i1 = sigmoidf_(gi1), f1 = sigmoidf_(gf1), o1 = sigmoidf_(go1), z1 = tanhf(gz1);
            c0s = i0 * z0 + f0 * c0s;
            c1s = i1 * z1 + f1 * c1s;
            float hv0 = o0 * tanhf(c0s);
            float hv1 = o1 * tanhf(c1s);
            *(float2*)&out[((size_t)ab * TT + t) * HID_ + j0 + ajp] = make_float2(hv0, hv1);
            __nv_bfloat16 h0 = __float2bfloat16(hv0);
            __nv_bfloat16 h1 = __float2bfloat16(hv1);
            __nv_bfloat16 l0 = __float2bfloat16(hv0 - __bfloat162float(h0));
            __nv_bfloat16 l1 = __float2bfloat16(hv1 - __bfloat162float(h1));
            u32 hw = (u32)__bfloat16_as_ushort(h0) | ((u32)__bfloat16_as_ushort(h1) << 16);
            u32 lw = (u32)__bfloat16_as_ushort(l0) | ((u32)__bfloat16_as_ushort(l1) << 16);
            *(u32*)&g_hbf[npn][0][ab][j0 + ajp] = hw;
            *(u32*)&g_hbf[npn][1][ab][j0 + ajp] = lw;
        }

        if (t + 1 < TT) grid_sync(phase);
    }
}

// ---------------- launch ----------------
extern "C" void kernel_launch(void* const* d_in, const int* in_sizes, int n_in,
                              void* d_out, int out_size) {
    const float* X   = (const float*)d_in[0];
    const float* Whi = (const float*)d_in[1];
    const float* Wxi = (const float*)d_in[2];
    const float* bi  = (const float*)d_in[3];
    const float* Whf = (const float*)d_in[4];
    const float* Wxf = (const float*)d_in[5];
    const float* bf  = (const float*)d_in[6];
    const float* Who = (const float*)d_in[7];
    const float* Wxo = (const float*)d_in[8];
    const float* bo  = (const float*)d_in[9];
    const float* Whz = (const float*)d_in[10];
    const float* Wxz = (const float*)d_in[11];
    const float* bz  = (const float*)d_in[12];

    pack_kernel<<<2048, 256>>>(X, Wxi, Wxf, Wxo, Wxz, Whi, Whf, Who, Whz, bi, bf, bo, bz);

    cudaFuncSetAttribute(xproj_kernel, cudaFuncAttributeMaxDynamicSharedMemorySize, XP_SMEM);
    dim3 gA(32, 256);
    xproj_kernel<<<gA, 512, XP_SMEM>>>();

    cudaFuncSetAttribute(lstm_kernel, cudaFuncAttributeMaxDynamicSharedMemorySize, SMEM_BYTES);
    lstm_kernel<<<NCTA, THR, SMEM_BYTES>>>((float*)d_out);
}

// round 7
// speedup vs baseline: 1.8624x; 1.1179x over previous
#include <cuda_runtime.h>
#include <cuda_bf16.h>
#include <cstdint>
#include <cstddef>

#define XD   512
#define HID_ 1024
#define BB   64
#define TT   512
#define G4   4096
#define MROWS 32768
#define NCTA 128
#define THR  256

typedef unsigned long long u64;
typedef unsigned int u32;

// ---------------- device scratch ----------------
__device__ float g_Wh4[(size_t)HID_ * G4];
__device__ float g_b4[G4];
__device__ float g_xproj[(size_t)MROWS * G4];                       // X@Wx + bias
__device__ __align__(16) __nv_bfloat16 g_hbf[2][2][BB][HID_];       // [parity][hi/lo][b][k]
__device__ __align__(16) __nv_bfloat16 g_XH[(size_t)MROWS * XD];
__device__ __align__(16) __nv_bfloat16 g_XL[(size_t)MROWS * XD];
__device__ __align__(16) __nv_bfloat16 g_WXH[(size_t)G4 * XD];
__device__ __align__(16) __nv_bfloat16 g_WXL[(size_t)G4 * XD];
__device__ unsigned g_bar_cnt;
__device__ volatile unsigned g_bar_phase;

// ---------------- helpers ----------------
#define SW128(x) ((x) ^ (((x) >> 3) & 0x70))

__device__ __forceinline__ u32 smem_u32(const void* p) {
    u32 a; asm("{ .reg .u64 t; cvta.to.shared.u64 t, %1; cvt.u32.u64 %0, t; }" : "=r"(a) : "l"(p));
    return a;
}
__device__ __forceinline__ void ldsm4(u32& r0, u32& r1, u32& r2, u32& r3, u32 addr) {
    asm volatile("ldmatrix.sync.aligned.m8n8.x4.shared.b16 {%0,%1,%2,%3}, [%4];"
                 : "=r"(r0), "=r"(r1), "=r"(r2), "=r"(r3) : "r"(addr));
}
__device__ __forceinline__ void mma16816(float* c, u32 a0, u32 a1, u32 a2, u32 a3, u32 b0, u32 b1) {
    asm volatile("mma.sync.aligned.m16n8k16.row.col.f32.bf16.bf16.f32 "
                 "{%0,%1,%2,%3}, {%4,%5,%6,%7}, {%8,%9}, {%0,%1,%2,%3};"
                 : "+f"(c[0]), "+f"(c[1]), "+f"(c[2]), "+f"(c[3])
                 : "r"(a0), "r"(a1), "r"(a2), "r"(a3), "r"(b0), "r"(b1));
}
__device__ __forceinline__ void cp_async16(u32 dst, const void* src) {
    asm volatile("cp.async.cg.shared.global [%0], [%1], 16;" :: "r"(dst), "l"(src) : "memory");
}
__device__ __forceinline__ void cp_commit() { asm volatile("cp.async.commit_group;" ::: "memory"); }
template<int N> __device__ __forceinline__ void cp_wait() {
    asm volatile("cp.async.wait_group %0;" :: "n"(N) : "memory");
}
__device__ __forceinline__ float sigmoidf_(float x) { return 1.f / (1.f + __expf(-x)); }

__device__ __forceinline__ void bsplit(float v, __nv_bfloat16& hi, __nv_bfloat16& lo) {
    hi = __float2bfloat16(v);
    lo = __float2bfloat16(v - __bfloat162float(hi));
}

// ---------------- kernel 0: pack Wh gate-major + build bf16 images ----------------
__global__ void pack_kernel(const float* __restrict__ X,
                            const float* __restrict__ Wxi, const float* __restrict__ Wxf,
                            const float* __restrict__ Wxo, const float* __restrict__ Wxz,
                            const float* __restrict__ Whi, const float* __restrict__ Whf,
                            const float* __restrict__ Who, const float* __restrict__ Whz,
                            const float* __restrict__ bi,  const float* __restrict__ bf,
                            const float* __restrict__ bo,  const float* __restrict__ bz) {
    int tid0 = blockIdx.x * blockDim.x + threadIdx.x;
    int stride = gridDim.x * blockDim.x;
    for (int idx = tid0; idx < HID_ * G4; idx += stride) {
        int k = idx >> 12, col = idx & 4095, g = col >> 10, j = col & 1023;
        const float* W = (g == 0) ? Whi : (g == 1) ? Whf : (g == 2) ? Who : Whz;
        g_Wh4[idx] = W[k * HID_ + j];
    }
    for (int idx = tid0; idx < G4; idx += stride) {
        int g = idx >> 10, j = idx & 1023;
        const float* b = (g == 0) ? bi : (g == 1) ? bf : (g == 2) ? bo : bz;
        g_b4[idx] = b[j];
    }
    for (int idx = tid0; idx < MROWS * (XD / 4); idx += stride) {
        int m = idx >> 7, kq = (idx & 127) * 4;
        float4 v = *(const float4*)&X[(size_t)m * XD + kq];
        __nv_bfloat16 h[4], l[4];
        bsplit(v.x, h[0], l[0]); bsplit(v.y, h[1], l[1]);
        bsplit(v.z, h[2], l[2]); bsplit(v.w, h[3], l[3]);
        int mt = m >> 7, mloc = m & 127, ck = kq >> 6, kloc = kq & 63;
        size_t off = (size_t)(mt * 8 + ck) * 16384 + (size_t)((mloc >> 3) << 10)
                   + (size_t)SW128(((mloc & 7) << 7) + (kloc << 1));
        *(uint2*)((char*)g_XH + off) = *(uint2*)h;
        *(uint2*)((char*)g_XL + off) = *(uint2*)l;
    }
    for (int idx = tid0; idx < G4 * (XD / 4); idx += stride) {
        int n = idx >> 7, kq = (idx & 127) * 4;
        int g = n >> 10, j = n & 1023;
        const float* W = (g == 0) ? Wxi : (g == 1) ? Wxf : (g == 2) ? Wxo : Wxz;
        __nv_bfloat16 h[4], l[4];
#pragma unroll
        for (int i = 0; i < 4; i++) bsplit(W[(size_t)(kq + i) * HID_ + j], h[i], l[i]);
        int nt = n >> 7, nloc = n & 127, ck = kq >> 6, kloc = kq & 63;
        size_t off = (size_t)(nt * 8 + ck) * 16384 + (size_t)((nloc >> 3) << 10)
                   + (size_t)SW128(((nloc & 7) << 7) + (kloc << 1));
        *(uint2*)((char*)g_WXH + off) = *(uint2*)h;
        *(uint2*)((char*)g_WXL + off) = *(uint2*)l;
    }
}

// ---------------- kernel A: xproj (HMMA bf16 3-product, cp.async pipeline) ----------------
#define XP_SMEM 131072

__global__ __launch_bounds__(512) void xproj_kernel() {
    extern __shared__ __align__(1024) char xs[];
    u32 smem_base = smem_u32(xs);
    int tid = threadIdx.x;
    int lane = tid & 31, wid = tid >> 5;
    int mw = wid & 3, nw = (wid >> 2) & 3;
    int ntb = blockIdx.x, mtb = blockIdx.y;

    int r128 = tid >> 7, lane128 = tid & 127;

    auto issue = [&](int ck, int stage) {
        size_t xb = (size_t)(mtb * 8 + ck) * 16384 + (size_t)lane128 * 16;
        size_t wb = (size_t)(ntb * 8 + ck) * 16384 + (size_t)lane128 * 16;
        const char* src = (r128 == 0) ? (const char*)g_XH + xb
                        : (r128 == 1) ? (const char*)g_XL + xb
                        : (r128 == 2) ? (const char*)g_WXH + wb
                                      : (const char*)g_WXL + wb;
        u32 dst = smem_base + stage * 65536 + r128 * 16384 + lane128 * 16;
#pragma unroll
        for (int q = 0; q < 8; q++) cp_async16(dst + q * 2048, src + q * 2048);
        cp_commit();
    };

    float acc[2][4][4];
#pragma unroll
    for (int i = 0; i < 2; i++)
#pragma unroll
        for (int j = 0; j < 4; j++)
#pragma unroll
            for (int q = 0; q < 4; q++) acc[i][j][q] = 0.f;

    issue(0, 0);

    int kbA = (lane & 16) ? 8 : 0;
    int kbB = lane & 8;
    int ar0 = mw * 32 + (lane & 15);
    int br0 = nw * 32 + (lane & 7) + ((lane & 16) ? 8 : 0);

    for (int ck = 0; ck < 8; ck++) {
        if (ck < 7) { issue(ck + 1, (ck + 1) & 1); cp_wait<1>(); }
        else cp_wait<0>();
        __syncthreads();
        u32 sb = smem_base + (ck & 1) * 65536;
#pragma unroll
        for (int ks = 0; ks < 4; ks++) {
            int klA = ks * 16 + kbA;
            int klB = ks * 16 + kbB;
            u32 ah[2][4], al[2][4], bh[2][4], bl[2][4];
#pragma unroll
            for (int mt2 = 0; mt2 < 2; mt2++) {
                int ar = ar0 + mt2 * 16;
                u32 aoff = (u32)((ar >> 3) << 10) + (u32)SW128(((ar & 7) << 7) + (klA << 1));
                ldsm4(ah[mt2][0], ah[mt2][1], ah[mt2][2], ah[mt2][3], sb + aoff);
                ldsm4(al[mt2][0], al[mt2][1], al[mt2][2], al[mt2][3], sb + 16384 + aoff);
            }
#pragma unroll
            for (int bg = 0; bg < 2; bg++) {
                int br = br0 + bg * 16;
                u32 boff = (u32)((br >> 3) << 10) + (u32)SW128(((br & 7) << 7) + (klB << 1));
                ldsm4(bh[bg][0], bh[bg][1], bh[bg][2], bh[bg][3], sb + 32768 + boff);
                ldsm4(bl[bg][0], bl[bg][1], bl[bg][2], bl[bg][3], sb + 49152 + boff);
            }
#pragma unroll
            for (int mt2 = 0; mt2 < 2; mt2++)
#pragma unroll
                for (int bg = 0; bg < 2; bg++) {
                    float* c0 = acc[mt2][bg * 2];
                    float* c1 = acc[mt2][bg * 2 + 1];
                    mma16816(c0, ah[mt2][0], ah[mt2][1], ah[mt2][2], ah[mt2][3], bh[bg][0], bh[bg][1]);
                    mma16816(c0, ah[mt2][0], ah[mt2][1], ah[mt2][2], ah[mt2][3], bl[bg][0], bl[bg][1]);
                    mma16816(c0, al[mt2][0], al[mt2][1], al[mt2][2], al[mt2][3], bh[bg][0], bh[bg][1]);
                    mma16816(c1, ah[mt2][0], ah[mt2][1], ah[mt2][2], ah[mt2][3], bh[bg][2], bh[bg][3]);
                    mma16816(c1, ah[mt2][0], ah[mt2][1], ah[mt2][2], ah[mt2][3], bl[bg][2], bl[bg][3]);
                    mma16816(c1, al[mt2][0], al[mt2][1], al[mt2][2], al[mt2][3], bh[bg][2], bh[bg][3]);
                }
        }
        __syncthreads();
    }

    int rowb = mtb * 128 + mw * 32;
    int colb = ntb * 128 + nw * 32;
    float2 bias[4];
#pragma unroll
    for (int nc = 0; nc < 4; nc++) {
        int col = colb + (nc >> 1) * 16 + (nc & 1) * 8 + (lane & 3) * 2;
        bias[nc] = *(const float2*)&g_b4[col];
    }
#pragma unroll
    for (int mt2 = 0; mt2 < 2; mt2++) {
        int r0 = rowb + mt2 * 16 + (lane >> 2);
#pragma unroll
        for (int nc = 0; nc < 4; nc++) {
            int col = colb + (nc >> 1) * 16 + (nc & 1) * 8 + (lane & 3) * 2;
            *(float2*)&g_xproj[(size_t)r0 * G4 + col] =
                make_float2(acc[mt2][nc][0] + bias[nc].x, acc[mt2][nc][1] + bias[nc].y);
            *(float2*)&g_xproj[(size_t)(r0 + 8) * G4 + col] =
                make_float2(acc[mt2][nc][2] + bias[nc].x, acc[mt2][nc][3] + bias[nc].y);
        }
    }
}

// ---------------- kernel B: persistent HMMA recurrence (K-split warps, dbl-buffered A) ----------------
// SMEM: [0,64K) Wh hi | [64K,128K) Wh lo | [128K,160K) Abuf0 {hi,lo} | [160K,192K) Abuf1 | [192K,+34.8K) gsum
#define WHI_OFF   0
#define WLO_OFF   65536
#define ABUF_OFF  131072
#define GSUM_OFF  196608
#define GROW      34
#define SMEM_BYTES (GSUM_OFF + 4 * BB * GROW * 4)

__device__ __forceinline__ void grid_sync(unsigned& phase) {
    __threadfence();
    __syncthreads();
    if (threadIdx.x == 0) {
        unsigned arrived = atomicAdd(&g_bar_cnt, 1u) + 1u;
        if (arrived == gridDim.x) {
            g_bar_cnt = 0;
            __threadfence();
            g_bar_phase = phase + 1u;
        } else {
            while (g_bar_phase == phase) { }
        }
        phase = phase + 1u;
        __threadfence();
    }
    __syncthreads();
}

__global__ __launch_bounds__(THR, 1) void lstm_kernel(float* __restrict__ out) {
    extern __shared__ __align__(1024) char sm[];
    u32 smem_base = smem_u32(sm);
    float* gsum = (float*)(sm + GSUM_OFF);
    int tid = threadIdx.x;
    int lane = tid & 31, wid = tid >> 5;
    int mt = wid & 1;                 // M-half: rows mt*32..+32
    int kq = wid >> 1;                // K-quarter within each 128-chunk: kq*32..+32
    int j0 = blockIdx.x * 8;

    // Wh slice hi/lo into SMEM atoms (8rows x 64cols, SW128)
    for (int idx = tid; idx < 32 * 1024; idx += THR) {
        int n = idx & 31, k = idx >> 5;
        int gc = (n >> 3) * 1024 + j0 + (n & 7);
        float wv = g_Wh4[(size_t)k * G4 + gc];
        __nv_bfloat16 hi = __float2bfloat16(wv);
        __nv_bfloat16 lo = __float2bfloat16(wv - __bfloat162float(hi));
        u32 off = (u32)((n >> 3) + ((k >> 6) << 2)) * 1024u
                + (u32)SW128(((n & 7) << 7) + ((k & 63) << 1));
        *(__nv_bfloat16*)(sm + WHI_OFF + off) = hi;
        *(__nv_bfloat16*)(sm + WLO_OFF + off) = lo;
    }

    int ab = tid >> 2;
    int ajp = (tid & 3) * 2;
    *(u32*)&g_hbf[0][0][ab][j0 + ajp] = 0u;
    *(u32*)&g_hbf[0][1][ab][j0 + ajp] = 0u;
    float c0s = 0.f, c1s = 0.f;

    // chunk loader precompute (256 thr x 4 uint4 per hi/lo = 32KB chunk)
    int ld_row[4]; int ld_kloc[4]; u32 sts_off[4];
#pragma unroll
    for (int q = 0; q < 4; q++) {
        int idx = q * 256 + tid;
        int b = idx >> 4, u = idx & 15, kloc = u * 8;
        ld_row[q] = b; ld_kloc[q] = kloc;
        sts_off[q] = (u32)((b >> 3) + ((kloc >> 6) << 3)) * 1024u
                   + (u32)SW128(((b & 7) << 7) + ((kloc & 63) << 1));
    }

    // mma fragment address components
    int arow_b = mt * 32 + (lane & 7) + (lane & 8);          // + sub*16
    int kbitA = (lane & 16) ? 8 : 0;
    int bcol_b = (lane & 7) + ((lane & 16) ? 8 : 0);         // + g16*16
    int kbitB = lane & 8;

    unsigned phase = 0;
    if (tid == 0) phase = g_bar_phase;
    grid_sync(phase);

    for (int t = 0; t < TT; t++) {
        int par = t & 1, npn = par ^ 1;
        const __nv_bfloat16* hhi = &g_hbf[par][0][0][0];
        const __nv_bfloat16* hlo = &g_hbf[par][1][0][0];

        float2 xpv[4];
        {
            size_t xb = ((size_t)ab * TT + t) * G4 + j0 + ajp;
#pragma unroll
            for (int g = 0; g < 4; g++)
                xpv[g] = *(const float2*)&g_xproj[xb + (size_t)g * 1024];
        }

        // prologue: load + stage chunk 0 into buf0
        uint4 rh[4], rl[4];
#pragma unroll
        for (int q = 0; q < 4; q++) {
            rh[q] = *(const uint4*)&hhi[ld_row[q] * 1024 + ld_kloc[q]];
            rl[q] = *(const uint4*)&hlo[ld_row[q] * 1024 + ld_kloc[q]];
        }
#pragma unroll
        for (int q = 0; q < 4; q++) {
            *(uint4*)(sm + ABUF_OFF + sts_off[q])         = rh[q];
            *(uint4*)(sm + ABUF_OFF + 16384 + sts_off[q]) = rl[q];
        }
        __syncthreads();

        float acc[2][4][4];
#pragma unroll
        for (int s = 0; s < 2; s++)
#pragma unroll
            for (int n = 0; n < 4; n++)
#pragma unroll
                for (int q = 0; q < 4; q++) acc[s][n][q] = 0.f;

#pragma unroll 1
        for (int ck = 0; ck < 8; ck++) {
            int buf = ck & 1;
            u32 abase = smem_base + ABUF_OFF + buf * 32768;
            // issue next-chunk loads early (hide L2 latency under mma)
            if (ck < 7) {
                int kc = (ck + 1) * 128;
#pragma unroll
                for (int q = 0; q < 4; q++) {
                    rh[q] = *(const uint4*)&hhi[ld_row[q] * 1024 + kc + ld_kloc[q]];
                    rl[q] = *(const uint4*)&hlo[ld_row[q] * 1024 + kc + ld_kloc[q]];
                }
            }
#pragma unroll
            for (int ks = 0; ks < 2; ks++) {
                int klA = kq * 32 + ks * 16 + kbitA;            // within-chunk k
                int kB = ck * 128 + kq * 32 + ks * 16 + kbitB;  // global k
                u32 ah[2][4], al[2][4], bh[2][4], bl[2][4];
#pragma unroll
                for (int sub = 0; sub < 2; sub++) {
                    int ar = arow_b + sub * 16;
                    u32 aoff = (u32)((ar >> 3) + ((klA >> 6) << 3)) * 1024u
                             + (u32)SW128(((ar & 7) << 7) + ((klA & 63) << 1));
                    ldsm4(ah[sub][0], ah[sub][1], ah[sub][2], ah[sub][3], abase + aoff);
                    ldsm4(al[sub][0], al[sub][1], al[sub][2], al[sub][3], abase + 16384 + aoff);
                }
#pragma unroll
                for (int g16 = 0; g16 < 2; g16++) {
                    int bc = bcol_b + g16 * 16;
                    u32 boff = (u32)((bc >> 3) + ((kB >> 6) << 2)) * 1024u
                             + (u32)SW128(((bc & 7) << 7) + ((kB & 63) << 1));
                    ldsm4(bh[g16][0], bh[g16][1], bh[g16][2], bh[g16][3], smem_base + WHI_OFF + boff);
                    ldsm4(bl[g16][0], bl[g16][1], bl[g16][2], bl[g16][3], smem_base + WLO_OFF + boff);
                }
#pragma unroll
                for (int sub = 0; sub < 2; sub++)
#pragma unroll
                    for (int g16 = 0; g16 < 2; g16++) {
                        float* c0 = acc[sub][g16 * 2];
                        float* c1 = acc[sub][g16 * 2 + 1];
                        mma16816(c0, ah[sub][0], ah[sub][1], ah[sub][2], ah[sub][3], bh[g16][0], bh[g16][1]);
                        mma16816(c0, ah[sub][0], ah[sub][1], ah[sub][2], ah[sub][3], bl[g16][0], bl[g16][1]);
                        mma16816(c0, al[sub][0], al[sub][1], al[sub][2], al[sub][3], bh[g16][0], bh[g16][1]);
                        mma16816(c1, ah[sub][0], ah[sub][1], ah[sub][2], ah[sub][3], bh[g16][2], bh[g16][3]);
                        mma16816(c1, ah[sub][0], ah[sub][1], ah[sub][2], ah[sub][3], bl[g16][2], bl[g16][3]);
                        mma16816(c1, al[sub][0], al[sub][1], al[sub][2], al[sub][3], bh[g16][2], bh[g16][3]);
                    }
            }
            // stage next chunk into other buffer (current readers done locally; sync covers CTA)
            if (ck < 7) {
                u32 nb = ABUF_OFF + (buf ^ 1) * 32768;
#pragma unroll
                for (int q = 0; q < 4; q++) {
                    *(uint4*)(sm + nb + sts_off[q])         = rh[q];
                    *(uint4*)(sm + nb + 16384 + sts_off[q]) = rl[q];
                }
            }
            __syncthreads();
        }

        // fragment writeback: per-warp K-quarter region
        {
            float* gq = gsum + (size_t)kq * BB * GROW;
#pragma unroll
            for (int sub = 0; sub < 2; sub++) {
                int r0 = mt * 32 + sub * 16 + (lane >> 2);
#pragma unroll
                for (int n8 = 0; n8 < 4; n8++) {
                    int cb = n8 * 8 + (lane & 3) * 2;
                    *(float2*)&gq[r0 * GROW + cb]       = make_float2(acc[sub][n8][0], acc[sub][n8][1]);
                    *(float2*)&gq[(r0 + 8) * GROW + cb] = make_float2(acc[sub][n8][2], acc[sub][n8][3]);
                }
            }
        }
        __syncthreads();

        // activation: 2 cells per thread, sum 4 K-quarters
        {
            float gg[4][2];
#pragma unroll
            for (int g = 0; g < 4; g++) { gg[g][0] = xpv[g].x; gg[g][1] = xpv[g].y; }
#pragma unroll
            for (int q = 0; q < 4; q++) {
                const float* gq = gsum + (size_t)q * BB * GROW + ab * GROW + ajp;
#pragma unroll
                for (int g = 0; g < 4; g++) {
                    float2 v = *(const float2*)&gq[g * 8];
                    gg[g][0] += v.x; gg[g][1] += v.y;
                }
            }
            float i0 = sigmoidf_(gg[0][0]), f0 = sigmoidf_(gg[1][0]), o0 = sigmoidf_(gg[2][0]), z0 = tanhf(gg[3][0]);
            float i1 = sigmoidf_(gg[0][1]), f1 = sigmoidf_(gg[1][1]), o1 = sigmoidf_(gg[2][1]), z1 = tanhf(gg[3][1]);
            c0s = i0 * z0 + f0 * c0s;
            c1s = i1 * z1 + f1 * c1s;
            float hv0 = o0 * tanhf(c0s);
            float hv1 = o1 * tanhf(c1s);
            *(float2*)&out[((size_t)ab * TT + t) * HID_ + j0 + ajp] = make_float2(hv0, hv1);
            __nv_bfloat16 h0 = __float2bfloat16(hv0);
            __nv_bfloat16 h1 = __float2bfloat16(hv1);
            __nv_bfloat16 l0 = __float2bfloat16(hv0 - __bfloat162float(h0));
            __nv_bfloat16 l1 = __float2bfloat16(hv1 - __bfloat162float(h1));
            u32 hw = (u32)__bfloat16_as_ushort(h0) | ((u32)__bfloat16_as_ushort(h1) << 16);
            u32 lw = (u32)__bfloat16_as_ushort(l0) | ((u32)__bfloat16_as_ushort(l1) << 16);
            *(u32*)&g_hbf[npn][0][ab][j0 + ajp] = hw;
            *(u32*)&g_hbf[npn][1][ab][j0 + ajp] = lw;
        }

        if (t + 1 < TT) grid_sync(phase);
    }
}

// ---------------- launch ----------------
extern "C" void kernel_launch(void* const* d_in, const int* in_sizes, int n_in,
                              void* d_out, int out_size) {
    const float* X   = (const float*)d_in[0];
    const float* Whi = (const float*)d_in[1];
    const float* Wxi = (const float*)d_in[2];
    const float* bi  = (const float*)d_in[3];
    const float* Whf = (const float*)d_in[4];
    const float* Wxf = (const float*)d_in[5];
    const float* bf  = (const float*)d_in[6];
    const float* Who = (const float*)d_in[7];
    const float* Wxo = (const float*)d_in[8];
    const float* bo  = (const float*)d_in[9];
    const float* Whz = (const float*)d_in[10];
    const float* Wxz = (const float*)d_in[11];
    const float* bz  = (const float*)d_in[12];

    pack_kernel<<<2048, 256>>>(X, Wxi, Wxf, Wxo, Wxz, Whi, Whf, Who, Whz, bi, bf, bo, bz);

    cudaFuncSetAttribute(xproj_kernel, cudaFuncAttributeMaxDynamicSharedMemorySize, XP_SMEM);
    dim3 gA(32, 256);
    xproj_kernel<<<gA, 512, XP_SMEM>>>();

    cudaFuncSetAttribute(lstm_kernel, cudaFuncAttributeMaxDynamicSharedMemorySize, SMEM_BYTES);
    lstm_kernel<<<NCTA, THR, SMEM_BYTES>>>((float*)d_out);
}

// round 8
// speedup vs baseline: 2.1845x; 1.1729x over previous
#include <cuda_runtime.h>
#include <cuda_bf16.h>
#include <cstdint>
#include <cstddef>

#define XD   512
#define HID_ 1024
#define BB   64
#define TT   512
#define G4   4096
#define MROWS 32768
#define NCTA 128
#define THR  256

typedef unsigned long long u64;
typedef unsigned int u32;

// ---------------- device scratch ----------------
__device__ float g_Wh4[(size_t)HID_ * G4];
__device__ float g_b4[G4];
__device__ float g_xproj[(size_t)MROWS * G4];                       // X@Wx + bias
// h stored directly in mma A-fragment layout: [parity][hi/lo][ktile(64)][mtile(4)][lane(32)] = uint4
__device__ __align__(16) uint4 g_hfrag[2][2][64][4][32];
__device__ __align__(16) __nv_bfloat16 g_XH[(size_t)MROWS * XD];
__device__ __align__(16) __nv_bfloat16 g_XL[(size_t)MROWS * XD];
__device__ __align__(16) __nv_bfloat16 g_WXH[(size_t)G4 * XD];
__device__ __align__(16) __nv_bfloat16 g_WXL[(size_t)G4 * XD];
__device__ unsigned g_bar_cnt;
__device__ volatile unsigned g_bar_phase;

// ---------------- helpers ----------------
#define SW128(x) ((x) ^ (((x) >> 3) & 0x70))

__device__ __forceinline__ u32 smem_u32(const void* p) {
    u32 a; asm("{ .reg .u64 t; cvta.to.shared.u64 t, %1; cvt.u32.u64 %0, t; }" : "=r"(a) : "l"(p));
    return a;
}
__device__ __forceinline__ void ldsm4(u32& r0, u32& r1, u32& r2, u32& r3, u32 addr) {
    asm volatile("ldmatrix.sync.aligned.m8n8.x4.shared.b16 {%0,%1,%2,%3}, [%4];"
                 : "=r"(r0), "=r"(r1), "=r"(r2), "=r"(r3) : "r"(addr));
}
__device__ __forceinline__ void mma16816(float* c, u32 a0, u32 a1, u32 a2, u32 a3, u32 b0, u32 b1) {
    asm volatile("mma.sync.aligned.m16n8k16.row.col.f32.bf16.bf16.f32 "
                 "{%0,%1,%2,%3}, {%4,%5,%6,%7}, {%8,%9}, {%0,%1,%2,%3};"
                 : "+f"(c[0]), "+f"(c[1]), "+f"(c[2]), "+f"(c[3])
                 : "r"(a0), "r"(a1), "r"(a2), "r"(a3), "r"(b0), "r"(b1));
}
__device__ __forceinline__ uint4 ldg_cg4(const uint4* p) {
    uint4 v;
    asm volatile("ld.global.cg.v4.u32 {%0,%1,%2,%3}, [%4];"
                 : "=r"(v.x), "=r"(v.y), "=r"(v.z), "=r"(v.w) : "l"(p));
    return v;
}
__device__ __forceinline__ void cp_async16(u32 dst, const void* src) {
    asm volatile("cp.async.cg.shared.global [%0], [%1], 16;" :: "r"(dst), "l"(src) : "memory");
}
__device__ __forceinline__ void cp_commit() { asm volatile("cp.async.commit_group;" ::: "memory"); }
template<int N> __device__ __forceinline__ void cp_wait() {
    asm volatile("cp.async.wait_group %0;" :: "n"(N) : "memory");
}
__device__ __forceinline__ float sigmoidf_(float x) { return 1.f / (1.f + __expf(-x)); }

__device__ __forceinline__ void bsplit(float v, __nv_bfloat16& hi, __nv_bfloat16& lo) {
    hi = __float2bfloat16(v);
    lo = __float2bfloat16(v - __bfloat162float(hi));
}

// ---------------- kernel 0: pack Wh gate-major + build bf16 images ----------------
__global__ void pack_kernel(const float* __restrict__ X,
                            const float* __restrict__ Wxi, const float* __restrict__ Wxf,
                            const float* __restrict__ Wxo, const float* __restrict__ Wxz,
                            const float* __restrict__ Whi, const float* __restrict__ Whf,
                            const float* __restrict__ Who, const float* __restrict__ Whz,
                            const float* __restrict__ bi,  const float* __restrict__ bf,
                            const float* __restrict__ bo,  const float* __restrict__ bz) {
    int tid0 = blockIdx.x * blockDim.x + threadIdx.x;
    int stride = gridDim.x * blockDim.x;
    for (int idx = tid0; idx < HID_ * G4; idx += stride) {
        int k = idx >> 12, col = idx & 4095, g = col >> 10, j = col & 1023;
        const float* W = (g == 0) ? Whi : (g == 1) ? Whf : (g == 2) ? Who : Whz;
        g_Wh4[idx] = W[k * HID_ + j];
    }
    for (int idx = tid0; idx < G4; idx += stride) {
        int g = idx >> 10, j = idx & 1023;
        const float* b = (g == 0) ? bi : (g == 1) ? bf : (g == 2) ? bo : bz;
        g_b4[idx] = b[j];
    }
    for (int idx = tid0; idx < MROWS * (XD / 4); idx += stride) {
        int m = idx >> 7, kq = (idx & 127) * 4;
        float4 v = *(const float4*)&X[(size_t)m * XD + kq];
        __nv_bfloat16 h[4], l[4];
        bsplit(v.x, h[0], l[0]); bsplit(v.y, h[1], l[1]);
        bsplit(v.z, h[2], l[2]); bsplit(v.w, h[3], l[3]);
        int mt = m >> 7, mloc = m & 127, ck = kq >> 6, kloc = kq & 63;
        size_t off = (size_t)(mt * 8 + ck) * 16384 + (size_t)((mloc >> 3) << 10)
                   + (size_t)SW128(((mloc & 7) << 7) + (kloc << 1));
        *(uint2*)((char*)g_XH + off) = *(uint2*)h;
        *(uint2*)((char*)g_XL + off) = *(uint2*)l;
    }
    for (int idx = tid0; idx < G4 * (XD / 4); idx += stride) {
        int n = idx >> 7, kq = (idx & 127) * 4;
        int g = n >> 10, j = n & 1023;
        const float* W = (g == 0) ? Wxi : (g == 1) ? Wxf : (g == 2) ? Wxo : Wxz;
        __nv_bfloat16 h[4], l[4];
#pragma unroll
        for (int i = 0; i < 4; i++) bsplit(W[(size_t)(kq + i) * HID_ + j], h[i], l[i]);
        int nt = n >> 7, nloc = n & 127, ck = kq >> 6, kloc = kq & 63;
        size_t off = (size_t)(nt * 8 + ck) * 16384 + (size_t)((nloc >> 3) << 10)
                   + (size_t)SW128(((nloc & 7) << 7) + (kloc << 1));
        *(uint2*)((char*)g_WXH + off) = *(uint2*)h;
        *(uint2*)((char*)g_WXL + off) = *(uint2*)l;
    }
}

// ---------------- kernel A: xproj (HMMA bf16 3-product, cp.async pipeline) ----------------
#define XP_SMEM 131072

__global__ __launch_bounds__(512) void xproj_kernel() {
    extern __shared__ __align__(1024) char xs[];
    u32 smem_base = smem_u32(xs);
    int tid = threadIdx.x;
    int lane = tid & 31, wid = tid >> 5;
    int mw = wid & 3, nw = (wid >> 2) & 3;
    int ntb = blockIdx.x, mtb = blockIdx.y;

    int r128 = tid >> 7, lane128 = tid & 127;

    auto issue = [&](int ck, int stage) {
        size_t xb = (size_t)(mtb * 8 + ck) * 16384 + (size_t)lane128 * 16;
        size_t wb = (size_t)(ntb * 8 + ck) * 16384 + (size_t)lane128 * 16;
        const char* src = (r128 == 0) ? (const char*)g_XH + xb
                        : (r128 == 1) ? (const char*)g_XL + xb
                        : (r128 == 2) ? (const char*)g_WXH + wb
                                      : (const char*)g_WXL + wb;
        u32 dst = smem_base + stage * 65536 + r128 * 16384 + lane128 * 16;
#pragma unroll
        for (int q = 0; q < 8; q++) cp_async16(dst + q * 2048, src + q * 2048);
        cp_commit();
    };

    float acc[2][4][4];
#pragma unroll
    for (int i = 0; i < 2; i++)
#pragma unroll
        for (int j = 0; j < 4; j++)
#pragma unroll
            for (int q = 0; q < 4; q++) acc[i][j][q] = 0.f;

    issue(0, 0);

    int kbA = (lane & 16) ? 8 : 0;
    int kbB = lane & 8;
    int ar0 = mw * 32 + (lane & 15);
    int br0 = nw * 32 + (lane & 7) + ((lane & 16) ? 8 : 0);

    for (int ck = 0; ck < 8; ck++) {
        if (ck < 7) { issue(ck + 1, (ck + 1) & 1); cp_wait<1>(); }
        else cp_wait<0>();
        __syncthreads();
        u32 sb = smem_base + (ck & 1) * 65536;
#pragma unroll
        for (int ks = 0; ks < 4; ks++) {
            int klA = ks * 16 + kbA;
            int klB = ks * 16 + kbB;
            u32 ah[2][4], al[2][4], bh[2][4], bl[2][4];
#pragma unroll
            for (int mt2 = 0; mt2 < 2; mt2++) {
                int ar = ar0 + mt2 * 16;
                u32 aoff = (u32)((ar >> 3) << 10) + (u32)SW128(((ar & 7) << 7) + (klA << 1));
                ldsm4(ah[mt2][0], ah[mt2][1], ah[mt2][2], ah[mt2][3], sb + aoff);
                ldsm4(al[mt2][0], al[mt2][1], al[mt2][2], al[mt2][3], sb + 16384 + aoff);
            }
#pragma unroll
            for (int bg = 0; bg < 2; bg++) {
                int br = br0 + bg * 16;
                u32 boff = (u32)((br >> 3) << 10) + (u32)SW128(((br & 7) << 7) + (klB << 1));
                ldsm4(bh[bg][0], bh[bg][1], bh[bg][2], bh[bg][3], sb + 32768 + boff);
                ldsm4(bl[bg][0], bl[bg][1], bl[bg][2], bl[bg][3], sb + 49152 + boff);
            }
#pragma unroll
            for (int mt2 = 0; mt2 < 2; mt2++)
#pragma unroll
                for (int bg = 0; bg < 2; bg++) {
                    float* c0 = acc[mt2][bg * 2];
                    float* c1 = acc[mt2][bg * 2 + 1];
                    mma16816(c0, ah[mt2][0], ah[mt2][1], ah[mt2][2], ah[mt2][3], bh[bg][0], bh[bg][1]);
                    mma16816(c0, ah[mt2][0], ah[mt2][1], ah[mt2][2], ah[mt2][3], bl[bg][0], bl[bg][1]);
                    mma16816(c0, al[mt2][0], al[mt2][1], al[mt2][2], al[mt2][3], bh[bg][0], bh[bg][1]);
                    mma16816(c1, ah[mt2][0], ah[mt2][1], ah[mt2][2], ah[mt2][3], bh[bg][2], bh[bg][3]);
                    mma16816(c1, ah[mt2][0], ah[mt2][1], ah[mt2][2], ah[mt2][3], bl[bg][2], bl[bg][3]);
                    mma16816(c1, al[mt2][0], al[mt2][1], al[mt2][2], al[mt2][3], bh[bg][2], bh[bg][3]);
                }
        }
        __syncthreads();
    }

    int rowb = mtb * 128 + mw * 32;
    int colb = ntb * 128 + nw * 32;
    float2 bias[4];
#pragma unroll
    for (int nc = 0; nc < 4; nc++) {
        int col = colb + (nc >> 1) * 16 + (nc & 1) * 8 + (lane & 3) * 2;
        bias[nc] = *(const float2*)&g_b4[col];
    }
#pragma unroll
    for (int mt2 = 0; mt2 < 2; mt2++) {
        int r0 = rowb + mt2 * 16 + (lane >> 2);
#pragma unroll
        for (int nc = 0; nc < 4; nc++) {
            int col = colb + (nc >> 1) * 16 + (nc & 1) * 8 + (lane & 3) * 2;
            *(float2*)&g_xproj[(size_t)r0 * G4 + col] =
                make_float2(acc[mt2][nc][0] + bias[nc].x, acc[mt2][nc][1] + bias[nc].y);
            *(float2*)&g_xproj[(size_t)(r0 + 8) * G4 + col] =
                make_float2(acc[mt2][nc][2] + bias[nc].x, acc[mt2][nc][3] + bias[nc].y);
        }
    }
}

// ---------------- kernel B: persistent HMMA recurrence (A direct from global fragments) ----------------
// SMEM: [0,64K) Wh hi | [64K,128K) Wh lo | [128K, +34.8K) gsum
#define WHI_OFF   0
#define WLO_OFF   65536
#define GSUM_OFF  131072
#define GROW      34
#define SMEM_BYTES (GSUM_OFF + 4 * BB * GROW * 4)

__device__ __forceinline__ void grid_sync(unsigned& phase) {
    __threadfence();
    __syncthreads();
    if (threadIdx.x == 0) {
        unsigned arrived = atomicAdd(&g_bar_cnt, 1u) + 1u;
        if (arrived == gridDim.x) {
            g_bar_cnt = 0;
            __threadfence();
            g_bar_phase = phase + 1u;
        } else {
            while (g_bar_phase == phase) { }
        }
        phase = phase + 1u;
        __threadfence();
    }
    __syncthreads();
}

__global__ __launch_bounds__(THR, 1) void lstm_kernel(float* __restrict__ out) {
    extern __shared__ __align__(1024) char sm[];
    u32 smem_base = smem_u32(sm);
    float* gsum = (float*)(sm + GSUM_OFF);
    int tid = threadIdx.x;
    int lane = tid & 31, wid = tid >> 5;
    int mt = wid & 1;                 // M-half: rows mt*32..+32
    int kq = wid >> 1;                // K-quarter within each 128-chunk
    int j0 = blockIdx.x * 8;

    // Wh slice hi/lo into SMEM atoms (8rows x 64cols, SW128) — loaded once, resident
    for (int idx = tid; idx < 32 * 1024; idx += THR) {
        int n = idx & 31, k = idx >> 5;
        int gc = (n >> 3) * 1024 + j0 + (n & 7);
        float wv = g_Wh4[(size_t)k * G4 + gc];
        __nv_bfloat16 hi = __float2bfloat16(wv);
        __nv_bfloat16 lo = __float2bfloat16(wv - __bfloat162float(hi));
        u32 off = (u32)((n >> 3) + ((k >> 6) << 2)) * 1024u
                + (u32)SW128(((n & 7) << 7) + ((k & 63) << 1));
        *(__nv_bfloat16*)(sm + WHI_OFF + off) = hi;
        *(__nv_bfloat16*)(sm + WLO_OFF + off) = lo;
    }

    // ---- activation thread ownership + fragment write slot ----
    int ab = tid >> 2;                     // batch row 0..63
    int ajp = (tid & 3) * 2;               // j pair within CTA's 8 cols
    int rm = ab & 15;
    int w_mtile = ab >> 4;
    int w_ktile = blockIdx.x >> 1;         // (j0+ajp)>>4
    int w_L = (rm & 7) * 4 + (tid & 3);
    int w_r = ((rm >> 3) & 1) + ((blockIdx.x & 1) << 1);
    u32* wp_hi = (u32*)&g_hfrag[0][0][w_ktile][w_mtile][w_L] + w_r;
    u32* wp_lo = (u32*)&g_hfrag[0][1][w_ktile][w_mtile][w_L] + w_r;
    const size_t PAR_STRIDE_U32 = 2ull * 64 * 4 * 32 * 4;   // one parity in u32 units
    // zero parity-0 image slots
    *wp_hi = 0u; *wp_lo = 0u;
    float c0s = 0.f, c1s = 0.f;

    // mma B fragment address components
    int bcol_b = (lane & 7) + ((lane & 16) ? 8 : 0);         // + g16*16
    int kbitB = lane & 8;

    unsigned phase = 0;
    if (tid == 0) phase = g_bar_phase;
    grid_sync(phase);

    for (int t = 0; t < TT; t++) {
        int par = t & 1, npn = par ^ 1;
        const uint4* fH = &g_hfrag[par][0][0][0][0];
        const uint4* fL = &g_hfrag[par][1][0][0][0];

        float2 xpv[4];
        {
            size_t xb = ((size_t)ab * TT + t) * G4 + j0 + ajp;
#pragma unroll
            for (int g = 0; g < 4; g++)
                xpv[g] = *(const float2*)&g_xproj[xb + (size_t)g * 1024];
        }

        float acc[2][4][4];
#pragma unroll
        for (int s = 0; s < 2; s++)
#pragma unroll
            for (int n = 0; n < 4; n++)
#pragma unroll
                for (int q = 0; q < 4; q++) acc[s][n][q] = 0.f;

        // A-fragment index helper: frag(kt, mtile) = (kt*4 + mtile)*32 + lane
        // prefetch chunk 0
        uint4 aH[2][2], aL[2][2], nH[2][2], nL[2][2];   // [ks][sub]
#pragma unroll
        for (int ks = 0; ks < 2; ks++) {
            int kt = kq * 2 + ks;
#pragma unroll
            for (int sub = 0; sub < 2; sub++) {
                int fi = (kt * 4 + (mt * 2 + sub)) * 32 + lane;
                aH[ks][sub] = ldg_cg4(fH + fi);
                aL[ks][sub] = ldg_cg4(fL + fi);
            }
        }

#pragma unroll 2
        for (int ck = 0; ck < 8; ck++) {
            // prefetch next chunk A fragments (overlaps with mma below)
            if (ck < 7) {
#pragma unroll
                for (int ks = 0; ks < 2; ks++) {
                    int kt = (ck + 1) * 8 + kq * 2 + ks;
#pragma unroll
                    for (int sub = 0; sub < 2; sub++) {
                        int fi = (kt * 4 + (mt * 2 + sub)) * 32 + lane;
                        nH[ks][sub] = ldg_cg4(fH + fi);
                        nL[ks][sub] = ldg_cg4(fL + fi);
                    }
                }
            }
#pragma unroll
            for (int ks = 0; ks < 2; ks++) {
                int kB = ck * 128 + kq * 32 + ks * 16 + kbitB;
                u32 bh[2][4], bl[2][4];
#pragma unroll
                for (int g16 = 0; g16 < 2; g16++) {
                    int bc = bcol_b + g16 * 16;
                    u32 boff = (u32)((bc >> 3) + ((kB >> 6) << 2)) * 1024u
                             + (u32)SW128(((bc & 7) << 7) + ((kB & 63) << 1));
                    ldsm4(bh[g16][0], bh[g16][1], bh[g16][2], bh[g16][3], smem_base + WHI_OFF + boff);
                    ldsm4(bl[g16][0], bl[g16][1], bl[g16][2], bl[g16][3], smem_base + WLO_OFF + boff);
                }
#pragma unroll
                for (int sub = 0; sub < 2; sub++) {
                    uint4 ah = aH[ks][sub], al = aL[ks][sub];
#pragma unroll
                    for (int g16 = 0; g16 < 2; g16++) {
                        float* c0 = acc[sub][g16 * 2];
                        float* c1 = acc[sub][g16 * 2 + 1];
                        mma16816(c0, ah.x, ah.y, ah.z, ah.w, bh[g16][0], bh[g16][1]);
                        mma16816(c0, ah.x, ah.y, ah.z, ah.w, bl[g16][0], bl[g16][1]);
                        mma16816(c0, al.x, al.y, al.z, al.w, bh[g16][0], bh[g16][1]);
                        mma16816(c1, ah.x, ah.y, ah.z, ah.w, bh[g16][2], bh[g16][3]);
                        mma16816(c1, ah.x, ah.y, ah.z, ah.w, bl[g16][2], bl[g16][3]);
                        mma16816(c1, al.x, al.y, al.z, al.w, bh[g16][2], bh[g16][3]);
                    }
                }
            }
#pragma unroll
            for (int ks = 0; ks < 2; ks++)
#pragma unroll
                for (int sub = 0; sub < 2; sub++) {
                    aH[ks][sub] = nH[ks][sub];
                    aL[ks][sub] = nL[ks][sub];
                }
        }

        // fragment writeback: per-warp K-quarter region
        {
            float* gq = gsum + (size_t)kq * BB * GROW;
#pragma unroll
            for (int sub = 0; sub < 2; sub++) {
                int r0 = mt * 32 + sub * 16 + (lane >> 2);
#pragma unroll
                for (int n8 = 0; n8 < 4; n8++) {
                    int cb = n8 * 8 + (lane & 3) * 2;
                    *(float2*)&gq[r0 * GROW + cb]       = make_float2(acc[sub][n8][0], acc[sub][n8][1]);
                    *(float2*)&gq[(r0 + 8) * GROW + cb] = make_float2(acc[sub][n8][2], acc[sub][n8][3]);
                }
            }
        }
        __syncthreads();

        // activation: 2 cells per thread, sum 4 K-quarters
        {
            float gg[4][2];
#pragma unroll
            for (int g = 0; g < 4; g++) { gg[g][0] = xpv[g].x; gg[g][1] = xpv[g].y; }
#pragma unroll
            for (int q = 0; q < 4; q++) {
                const float* gq = gsum + (size_t)q * BB * GROW + ab * GROW + ajp;
#pragma unroll
                for (int g = 0; g < 4; g++) {
                    float2 v = *(const float2*)&gq[g * 8];
                    gg[g][0] += v.x; gg[g][1] += v.y;
                }
            }
            float i0 = sigmoidf_(gg[0][0]), f0 = sigmoidf_(gg[1][0]), o0 = sigmoidf_(gg[2][0]), z0 = tanhf(gg[3][0]);
            float i1 = sigmoidf_(gg[0][1]), f1 = sigmoidf_(gg[1][1]), o1 = sigmoidf_(gg[2][1]), z1 = tanhf(gg[3][1]);
            c0s = i0 * z0 + f0 * c0s;
            c1s = i1 * z1 + f1 * c1s;
            float hv0 = o0 * tanhf(c0s);
            float hv1 = o1 * tanhf(c1s);
            *(float2*)&out[((size_t)ab * TT + t) * HID_ + j0 + ajp] = make_float2(hv0, hv1);
            __nv_bfloat16 h0 = __float2bfloat16(hv0);
            __nv_bfloat16 h1 = __float2bfloat16(hv1);
            __nv_bfloat16 l0 = __float2bfloat16(hv0 - __bfloat162float(h0));
            __nv_bfloat16 l1 = __float2bfloat16(hv1 - __bfloat162float(h1));
            u32 hw = (u32)__bfloat16_as_ushort(h0) | ((u32)__bfloat16_as_ushort(h1) << 16);
            u32 lw = (u32)__bfloat16_as_ushort(l0) | ((u32)__bfloat16_as_ushort(l1) << 16);
            wp_hi[(size_t)npn * PAR_STRIDE_U32] = hw;
            wp_lo[(size_t)npn * PAR_STRIDE_U32] = lw;
        }

        if (t + 1 < TT) grid_sync(phase);
    }
}

// ---------------- launch ----------------
extern "C" void kernel_launch(void* const* d_in, const int* in_sizes, int n_in,
                              void* d_out, int out_size) {
    const float* X   = (const float*)d_in[0];
    const float* Whi = (const float*)d_in[1];
    const float* Wxi = (const float*)d_in[2];
    const float* bi  = (const float*)d_in[3];
    const float* Whf = (const float*)d_in[4];
    const float* Wxf = (const float*)d_in[5];
    const float* bf  = (const float*)d_in[6];
    const float* Who = (const float*)d_in[7];
    const float* Wxo = (const float*)d_in[8];
    const float* bo  = (const float*)d_in[9];
    const float* Whz = (const float*)d_in[10];
    const float* Wxz = (const float*)d_in[11];
    const float* bz  = (const float*)d_in[12];

    pack_kernel<<<2048, 256>>>(X, Wxi, Wxf, Wxo, Wxz, Whi, Whf, Who, Whz, bi, bf, bo, bz);

    cudaFuncSetAttribute(xproj_kernel, cudaFuncAttributeMaxDynamicSharedMemorySize, XP_SMEM);
    dim3 gA(32, 256);
    xproj_kernel<<<gA, 512, XP_SMEM>>>();

    cudaFuncSetAttribute(lstm_kernel, cudaFuncAttributeMaxDynamicSharedMemorySize, SMEM_BYTES);
    lstm_kernel<<<NCTA, THR, SMEM_BYTES>>>((float*)d_out);
}

// round 9
// speedup vs baseline: 2.4383x; 1.1162x over previous
#include <cuda_runtime.h>
#include <cuda_bf16.h>
#include <cuda_fp16.h>
#include <cstdint>
#include <cstddef>

#define XD   512
#define HID_ 1024
#define BB   64
#define TT   512
#define G4   4096
#define MROWS 32768
#define NCTA 128
#define THR  256

typedef unsigned long long u64;
typedef unsigned int u32;

// ---------------- device scratch ----------------
__device__ float g_Wh4[(size_t)HID_ * G4];
__device__ float g_b4[G4];
__device__ float g_xproj[(size_t)MROWS * G4];                       // X@Wx + bias
// h stored directly in mma A-fragment layout (single fp16 image): [parity][ktile(64)][mtile(4)][lane(32)]
__device__ __align__(16) uint4 g_hfrag[2][64][4][32];
__device__ __align__(16) __nv_bfloat16 g_XH[(size_t)MROWS * XD];
__device__ __align__(16) __nv_bfloat16 g_XL[(size_t)MROWS * XD];
__device__ __align__(16) __nv_bfloat16 g_WXH[(size_t)G4 * XD];
__device__ __align__(16) __nv_bfloat16 g_WXL[(size_t)G4 * XD];
__device__ unsigned g_bar_cnt;
__device__ volatile unsigned g_bar_phase;

// ---------------- helpers ----------------
#define SW128(x) ((x) ^ (((x) >> 3) & 0x70))

__device__ __forceinline__ u32 smem_u32(const void* p) {
    u32 a; asm("{ .reg .u64 t; cvta.to.shared.u64 t, %1; cvt.u32.u64 %0, t; }" : "=r"(a) : "l"(p));
    return a;
}
__device__ __forceinline__ void ldsm4(u32& r0, u32& r1, u32& r2, u32& r3, u32 addr) {
    asm volatile("ldmatrix.sync.aligned.m8n8.x4.shared.b16 {%0,%1,%2,%3}, [%4];"
                 : "=r"(r0), "=r"(r1), "=r"(r2), "=r"(r3) : "r"(addr));
}
__device__ __forceinline__ void mma16816bf(float* c, u32 a0, u32 a1, u32 a2, u32 a3, u32 b0, u32 b1) {
    asm volatile("mma.sync.aligned.m16n8k16.row.col.f32.bf16.bf16.f32 "
                 "{%0,%1,%2,%3}, {%4,%5,%6,%7}, {%8,%9}, {%0,%1,%2,%3};"
                 : "+f"(c[0]), "+f"(c[1]), "+f"(c[2]), "+f"(c[3])
                 : "r"(a0), "r"(a1), "r"(a2), "r"(a3), "r"(b0), "r"(b1));
}
__device__ __forceinline__ void mma16816h(float* c, u32 a0, u32 a1, u32 a2, u32 a3, u32 b0, u32 b1) {
    asm volatile("mma.sync.aligned.m16n8k16.row.col.f32.f16.f16.f32 "
                 "{%0,%1,%2,%3}, {%4,%5,%6,%7}, {%8,%9}, {%0,%1,%2,%3};"
                 : "+f"(c[0]), "+f"(c[1]), "+f"(c[2]), "+f"(c[3])
                 : "r"(a0), "r"(a1), "r"(a2), "r"(a3), "r"(b0), "r"(b1));
}
__device__ __forceinline__ uint4 ldg_cg4(const uint4* p) {
    uint4 v;
    asm volatile("ld.global.cg.v4.u32 {%0,%1,%2,%3}, [%4];"
                 : "=r"(v.x), "=r"(v.y), "=r"(v.z), "=r"(v.w) : "l"(p));
    return v;
}
__device__ __forceinline__ void cp_async16(u32 dst, const void* src) {
    asm volatile("cp.async.cg.shared.global [%0], [%1], 16;" :: "r"(dst), "l"(src) : "memory");
}
__device__ __forceinline__ void cp_commit() { asm volatile("cp.async.commit_group;" ::: "memory"); }
template<int N> __device__ __forceinline__ void cp_wait() {
    asm volatile("cp.async.wait_group %0;" :: "n"(N) : "memory");
}
__device__ __forceinline__ float sigmoidf_(float x) { return 1.f / (1.f + __expf(-x)); }

__device__ __forceinline__ void bsplit(float v, __nv_bfloat16& hi, __nv_bfloat16& lo) {
    hi = __float2bfloat16(v);
    lo = __float2bfloat16(v - __bfloat162float(hi));
}

// ---------------- kernel 0: pack Wh gate-major + build bf16 images ----------------
__global__ void pack_kernel(const float* __restrict__ X,
                            const float* __restrict__ Wxi, const float* __restrict__ Wxf,
                            const float* __restrict__ Wxo, const float* __restrict__ Wxz,
                            const float* __restrict__ Whi, const float* __restrict__ Whf,
                            const float* __restrict__ Who, const float* __restrict__ Whz,
                            const float* __restrict__ bi,  const float* __restrict__ bf,
                            const float* __restrict__ bo,  const float* __restrict__ bz) {
    int tid0 = blockIdx.x * blockDim.x + threadIdx.x;
    int stride = gridDim.x * blockDim.x;
    for (int idx = tid0; idx < HID_ * G4; idx += stride) {
        int k = idx >> 12, col = idx & 4095, g = col >> 10, j = col & 1023;
        const float* W = (g == 0) ? Whi : (g == 1) ? Whf : (g == 2) ? Who : Whz;
        g_Wh4[idx] = W[k * HID_ + j];
    }
    for (int idx = tid0; idx < G4; idx += stride) {
        int g = idx >> 10, j = idx & 1023;
        const float* b = (g == 0) ? bi : (g == 1) ? bf : (g == 2) ? bo : bz;
        g_b4[idx] = b[j];
    }
    for (int idx = tid0; idx < MROWS * (XD / 4); idx += stride) {
        int m = idx >> 7, kq = (idx & 127) * 4;
        float4 v = *(const float4*)&X[(size_t)m * XD + kq];
        __nv_bfloat16 h[4], l[4];
        bsplit(v.x, h[0], l[0]); bsplit(v.y, h[1], l[1]);
        bsplit(v.z, h[2], l[2]); bsplit(v.w, h[3], l[3]);
        int mt = m >> 7, mloc = m & 127, ck = kq >> 6, kloc = kq & 63;
        size_t off = (size_t)(mt * 8 + ck) * 16384 + (size_t)((mloc >> 3) << 10)
                   + (size_t)SW128(((mloc & 7) << 7) + (kloc << 1));
        *(uint2*)((char*)g_XH + off) = *(uint2*)h;
        *(uint2*)((char*)g_XL + off) = *(uint2*)l;
    }
    for (int idx = tid0; idx < G4 * (XD / 4); idx += stride) {
        int n = idx >> 7, kq = (idx & 127) * 4;
        int g = n >> 10, j = n & 1023;
        const float* W = (g == 0) ? Wxi : (g == 1) ? Wxf : (g == 2) ? Wxo : Wxz;
        __nv_bfloat16 h[4], l[4];
#pragma unroll
        for (int i = 0; i < 4; i++) bsplit(W[(size_t)(kq + i) * HID_ + j], h[i], l[i]);
        int nt = n >> 7, nloc = n & 127, ck = kq >> 6, kloc = kq & 63;
        size_t off = (size_t)(nt * 8 + ck) * 16384 + (size_t)((nloc >> 3) << 10)
                   + (size_t)SW128(((nloc & 7) << 7) + (kloc << 1));
        *(uint2*)((char*)g_WXH + off) = *(uint2*)h;
        *(uint2*)((char*)g_WXL + off) = *(uint2*)l;
    }
}

// ---------------- kernel A: xproj (HMMA bf16 3-product, cp.async pipeline) ----------------
#define XP_SMEM 131072

__global__ __launch_bounds__(512) void xproj_kernel() {
    extern __shared__ __align__(1024) char xs[];
    u32 smem_base = smem_u32(xs);
    int tid = threadIdx.x;
    int lane = tid & 31, wid = tid >> 5;
    int mw = wid & 3, nw = (wid >> 2) & 3;
    int ntb = blockIdx.x, mtb = blockIdx.y;

    int r128 = tid >> 7, lane128 = tid & 127;

    auto issue = [&](int ck, int stage) {
        size_t xb = (size_t)(mtb * 8 + ck) * 16384 + (size_t)lane128 * 16;
        size_t wb = (size_t)(ntb * 8 + ck) * 16384 + (size_t)lane128 * 16;
        const char* src = (r128 == 0) ? (const char*)g_XH + xb
                        : (r128 == 1) ? (const char*)g_XL + xb
                        : (r128 == 2) ? (const char*)g_WXH + wb
                                      : (const char*)g_WXL + wb;
        u32 dst = smem_base + stage * 65536 + r128 * 16384 + lane128 * 16;
#pragma unroll
        for (int q = 0; q < 8; q++) cp_async16(dst + q * 2048, src + q * 2048);
        cp_commit();
    };

    float acc[2][4][4];
#pragma unroll
    for (int i = 0; i < 2; i++)
#pragma unroll
        for (int j = 0; j < 4; j++)
#pragma unroll
            for (int q = 0; q < 4; q++) acc[i][j][q] = 0.f;

    issue(0, 0);

    int kbA = (lane & 16) ? 8 : 0;
    int kbB = lane & 8;
    int ar0 = mw * 32 + (lane & 15);
    int br0 = nw * 32 + (lane & 7) + ((lane & 16) ? 8 : 0);

    for (int ck = 0; ck < 8; ck++) {
        if (ck < 7) { issue(ck + 1, (ck + 1) & 1); cp_wait<1>(); }
        else cp_wait<0>();
        __syncthreads();
        u32 sb = smem_base + (ck & 1) * 65536;
#pragma unroll
        for (int ks = 0; ks < 4; ks++) {
            int klA = ks * 16 + kbA;
            int klB = ks * 16 + kbB;
            u32 ah[2][4], al[2][4], bh[2][4], bl[2][4];
#pragma unroll
            for (int mt2 = 0; mt2 < 2; mt2++) {
                int ar = ar0 + mt2 * 16;
                u32 aoff = (u32)((ar >> 3) << 10) + (u32)SW128(((ar & 7) << 7) + (klA << 1));
                ldsm4(ah[mt2][0], ah[mt2][1], ah[mt2][2], ah[mt2][3], sb + aoff);
                ldsm4(al[mt2][0], al[mt2][1], al[mt2][2], al[mt2][3], sb + 16384 + aoff);
            }
#pragma unroll
            for (int bg = 0; bg < 2; bg++) {
                int br = br0 + bg * 16;
                u32 boff = (u32)((br >> 3) << 10) + (u32)SW128(((br & 7) << 7) + (klB << 1));
                ldsm4(bh[bg][0], bh[bg][1], bh[bg][2], bh[bg][3], sb + 32768 + boff);
                ldsm4(bl[bg][0], bl[bg][1], bl[bg][2], bl[bg][3], sb + 49152 + boff);
            }
#pragma unroll
            for (int mt2 = 0; mt2 < 2; mt2++)
#pragma unroll
                for (int bg = 0; bg < 2; bg++) {
                    float* c0 = acc[mt2][bg * 2];
                    float* c1 = acc[mt2][bg * 2 + 1];
                    mma16816bf(c0, ah[mt2][0], ah[mt2][1], ah[mt2][2], ah[mt2][3], bh[bg][0], bh[bg][1]);
                    mma16816bf(c0, ah[mt2][0], ah[mt2][1], ah[mt2][2], ah[mt2][3], bl[bg][0], bl[bg][1]);
                    mma16816bf(c0, al[mt2][0], al[mt2][1], al[mt2][2], al[mt2][3], bh[bg][0], bh[bg][1]);
                    mma16816bf(c1, ah[mt2][0], ah[mt2][1], ah[mt2][2], ah[mt2][3], bh[bg][2], bh[bg][3]);
                    mma16816bf(c1, ah[mt2][0], ah[mt2][1], ah[mt2][2], ah[mt2][3], bl[bg][2], bl[bg][3]);
                    mma16816bf(c1, al[mt2][0], al[mt2][1], al[mt2][2], al[mt2][3], bh[bg][2], bh[bg][3]);
                }
        }
        __syncthreads();
    }

    int rowb = mtb * 128 + mw * 32;
    int colb = ntb * 128 + nw * 32;
    float2 bias[4];
#pragma unroll
    for (int nc = 0; nc < 4; nc++) {
        int col = colb + (nc >> 1) * 16 + (nc & 1) * 8 + (lane & 3) * 2;
        bias[nc] = *(const float2*)&g_b4[col];
    }
#pragma unroll
    for (int mt2 = 0; mt2 < 2; mt2++) {
        int r0 = rowb + mt2 * 16 + (lane >> 2);
#pragma unroll
        for (int nc = 0; nc < 4; nc++) {
            int col = colb + (nc >> 1) * 16 + (nc & 1) * 8 + (lane & 3) * 2;
            *(float2*)&g_xproj[(size_t)r0 * G4 + col] =
                make_float2(acc[mt2][nc][0] + bias[nc].x, acc[mt2][nc][1] + bias[nc].y);
            *(float2*)&g_xproj[(size_t)(r0 + 8) * G4 + col] =
                make_float2(acc[mt2][nc][2] + bias[nc].x, acc[mt2][nc][3] + bias[nc].y);
        }
    }
}

// ---------------- kernel B: persistent HMMA recurrence (fp16 2-product, A direct from global) ----------------
// SMEM: [0,64K) Wh hi(fp16) | [64K,128K) Wh lo(fp16) | [128K, +34.8K) gsum
#define WHI_OFF   0
#define WLO_OFF   65536
#define GSUM_OFF  131072
#define GROW      34
#define SMEM_BYTES (GSUM_OFF + 4 * BB * GROW * 4)

__device__ __forceinline__ void grid_sync(unsigned& phase) {
    __threadfence();
    __syncthreads();
    if (threadIdx.x == 0) {
        unsigned arrived = atomicAdd(&g_bar_cnt, 1u) + 1u;
        if (arrived == gridDim.x) {
            g_bar_cnt = 0;
            __threadfence();
            g_bar_phase = phase + 1u;
        } else {
            while (g_bar_phase == phase) { }
        }
        phase = phase + 1u;
        __threadfence();
    }
    __syncthreads();
}

__global__ __launch_bounds__(THR, 1) void lstm_kernel(float* __restrict__ out) {
    extern __shared__ __align__(1024) char sm[];
    u32 smem_base = smem_u32(sm);
    float* gsum = (float*)(sm + GSUM_OFF);
    int tid = threadIdx.x;
    int lane = tid & 31, wid = tid >> 5;
    int mt = wid & 1;                 // M-half
    int kq = wid >> 1;                // K-quarter
    int j0 = blockIdx.x * 8;

    // Wh slice -> fp16 hi/lo into SMEM atoms (8rows x 64cols, SW128); exact split (2^-22)
    for (int idx = tid; idx < 32 * 1024; idx += THR) {
        int n = idx & 31, k = idx >> 5;
        int gc = (n >> 3) * 1024 + j0 + (n & 7);
        float wv = g_Wh4[(size_t)k * G4 + gc];
        __half hi = __float2half_rn(wv);
        __half lo = __float2half_rn(wv - __half2float(hi));
        u32 off = (u32)((n >> 3) + ((k >> 6) << 2)) * 1024u
                + (u32)SW128(((n & 7) << 7) + ((k & 63) << 1));
        *(__half*)(sm + WHI_OFF + off) = hi;
        *(__half*)(sm + WLO_OFF + off) = lo;
    }

    // ---- activation thread ownership + fragment write slot (single fp16 image) ----
    int ab = tid >> 2;                     // batch row 0..63
    int ajp = (tid & 3) * 2;               // j pair within CTA's 8 cols
    int rm = ab & 15;
    int w_mtile = ab >> 4;
    int w_ktile = blockIdx.x >> 1;         // (j0+ajp)>>4
    int w_L = (rm & 7) * 4 + (tid & 3);
    int w_r = ((rm >> 3) & 1) + ((blockIdx.x & 1) << 1);
    u32* wp = (u32*)&g_hfrag[0][w_ktile][w_mtile][w_L] + w_r;
    const size_t PAR_STRIDE_U32 = 64ull * 4 * 32 * 4;   // one parity in u32 units
    *wp = 0u;                              // zero parity-0 image
    float c0s = 0.f, c1s = 0.f;

    // mma B fragment address components
    int bcol_b = (lane & 7) + ((lane & 16) ? 8 : 0);
    int kbitB = lane & 8;

    unsigned phase = 0;
    if (tid == 0) phase = g_bar_phase;
    grid_sync(phase);

    for (int t = 0; t < TT; t++) {
        int par = t & 1, npn = par ^ 1;
        const uint4* fH = &g_hfrag[par][0][0][0];

        float2 xpv[4];
        {
            size_t xb = ((size_t)ab * TT + t) * G4 + j0 + ajp;
#pragma unroll
            for (int g = 0; g < 4; g++)
                xpv[g] = *(const float2*)&g_xproj[xb + (size_t)g * 1024];
        }

        float acc[2][4][4];
#pragma unroll
        for (int s = 0; s < 2; s++)
#pragma unroll
            for (int n = 0; n < 4; n++)
#pragma unroll
                for (int q = 0; q < 4; q++) acc[s][n][q] = 0.f;

        // prefetch chunk 0 A fragments
        uint4 aH[2][2], nH[2][2];   // [ks][sub]
#pragma unroll
        for (int ks = 0; ks < 2; ks++) {
            int kt = kq * 2 + ks;
#pragma unroll
            for (int sub = 0; sub < 2; sub++)
                aH[ks][sub] = ldg_cg4(fH + (kt * 4 + (mt * 2 + sub)) * 32 + lane);
        }

#pragma unroll 2
        for (int ck = 0; ck < 8; ck++) {
            if (ck < 7) {
#pragma unroll
                for (int ks = 0; ks < 2; ks++) {
                    int kt = (ck + 1) * 8 + kq * 2 + ks;
#pragma unroll
                    for (int sub = 0; sub < 2; sub++)
                        nH[ks][sub] = ldg_cg4(fH + (kt * 4 + (mt * 2 + sub)) * 32 + lane);
                }
            }
#pragma unroll
            for (int ks = 0; ks < 2; ks++) {
                int kB = ck * 128 + kq * 32 + ks * 16 + kbitB;
                u32 bh[2][4], bl[2][4];
#pragma unroll
                for (int g16 = 0; g16 < 2; g16++) {
                    int bc = bcol_b + g16 * 16;
                    u32 boff = (u32)((bc >> 3) + ((kB >> 6) << 2)) * 1024u
                             + (u32)SW128(((bc & 7) << 7) + ((kB & 63) << 1));
                    ldsm4(bh[g16][0], bh[g16][1], bh[g16][2], bh[g16][3], smem_base + WHI_OFF + boff);
                    ldsm4(bl[g16][0], bl[g16][1], bl[g16][2], bl[g16][3], smem_base + WLO_OFF + boff);
                }
#pragma unroll
                for (int sub = 0; sub < 2; sub++) {
                    uint4 ah = aH[ks][sub];
#pragma unroll
                    for (int g16 = 0; g16 < 2; g16++) {
                        float* c0 = acc[sub][g16 * 2];
                        float* c1 = acc[sub][g16 * 2 + 1];
                        mma16816h(c0, ah.x, ah.y, ah.z, ah.w, bh[g16][0], bh[g16][1]);
                        mma16816h(c0, ah.x, ah.y, ah.z, ah.w, bl[g16][0], bl[g16][1]);
                        mma16816h(c1, ah.x, ah.y, ah.z, ah.w, bh[g16][2], bh[g16][3]);
                        mma16816h(c1, ah.x, ah.y, ah.z, ah.w, bl[g16][2], bl[g16][3]);
                    }
                }
            }
#pragma unroll
            for (int ks = 0; ks < 2; ks++)
#pragma unroll
                for (int sub = 0; sub < 2; sub++)
                    aH[ks][sub] = nH[ks][sub];
        }

        // fragment writeback: per-warp K-quarter region
        {
            float* gq = gsum + (size_t)kq * BB * GROW;
#pragma unroll
            for (int sub = 0; sub < 2; sub++) {
                int r0 = mt * 32 + sub * 16 + (lane >> 2);
#pragma unroll
                for (int n8 = 0; n8 < 4; n8++) {
                    int cb = n8 * 8 + (lane & 3) * 2;
                    *(float2*)&gq[r0 * GROW + cb]       = make_float2(acc[sub][n8][0], acc[sub][n8][1]);
                    *(float2*)&gq[(r0 + 8) * GROW + cb] = make_float2(acc[sub][n8][2], acc[sub][n8][3]);
                }
            }
        }
        __syncthreads();

        // activation: 2 cells per thread, sum 4 K-quarters
        {
            float gg[4][2];
#pragma unroll
            for (int g = 0; g < 4; g++) { gg[g][0] = xpv[g].x; gg[g][1] = xpv[g].y; }
#pragma unroll
            for (int q = 0; q < 4; q++) {
                const float* gq = gsum + (size_t)q * BB * GROW + ab * GROW + ajp;
#pragma unroll
                for (int g = 0; g < 4; g++) {
                    float2 v = *(const float2*)&gq[g * 8];
                    gg[g][0] += v.x; gg[g][1] += v.y;
                }
            }
            float i0 = sigmoidf_(gg[0][0]), f0 = sigmoidf_(gg[1][0]), o0 = sigmoidf_(gg[2][0]), z0 = tanhf(gg[3][0]);
            float i1 = sigmoidf_(gg[0][1]), f1 = sigmoidf_(gg[1][1]), o1 = sigmoidf_(gg[2][1]), z1 = tanhf(gg[3][1]);
            c0s = i0 * z0 + f0 * c0s;
            c1s = i1 * z1 + f1 * c1s;
            float hv0 = o0 * tanhf(c0s);
            float hv1 = o1 * tanhf(c1s);
            *(float2*)&out[((size_t)ab * TT + t) * HID_ + j0 + ajp] = make_float2(hv0, hv1);
            __half h0 = __float2half_rn(hv0);
            __half h1 = __float2half_rn(hv1);
            u32 hw = (u32)__half_as_ushort(h0) | ((u32)__half_as_ushort(h1) << 16);
            wp[(size_t)npn * PAR_STRIDE_U32] = hw;
        }

        if (t + 1 < TT) grid_sync(phase);
    }
}

// ---------------- launch ----------------
extern "C" void kernel_launch(void* const* d_in, const int* in_sizes, int n_in,
                              void* d_out, int out_size) {
    const float* X   = (const float*)d_in[0];
    const float* Whi = (const float*)d_in[1];
    const float* Wxi = (const float*)d_in[2];
    const float* bi  = (const float*)d_in[3];
    const float* Whf = (const float*)d_in[4];
    const float* Wxf = (const float*)d_in[5];
    const float* bf  = (const float*)d_in[6];
    const float* Who = (const float*)d_in[7];
    const float* Wxo = (const float*)d_in[8];
    const float* bo  = (const float*)d_in[9];
    const float* Whz = (const float*)d_in[10];
    const float* Wxz = (const float*)d_in[11];
    const float* bz  = (const float*)d_in[12];

    pack_kernel<<<2048, 256>>>(X, Wxi, Wxf, Wxo, Wxz, Whi, Whf, Who, Whz, bi, bf, bo, bz);

    cudaFuncSetAttribute(xproj_kernel, cudaFuncAttributeMaxDynamicSharedMemorySize, XP_SMEM);
    dim3 gA(32, 256);
    xproj_kernel<<<gA, 512, XP_SMEM>>>();

    cudaFuncSetAttribute(lstm_kernel, cudaFuncAttributeMaxDynamicSharedMemorySize, SMEM_BYTES);
    lstm_kernel<<<NCTA, THR, SMEM_BYTES>>>((float*)d_out);
}

// round 10
// speedup vs baseline: 2.8570x; 1.1717x over previous
#include <cuda_runtime.h>
#include <cuda_bf16.h>
#include <cuda_fp16.h>
#include <cstdint>
#include <cstddef>

#define XD   512
#define HID_ 1024
#define BB   64
#define TT   512
#define G4   4096
#define MROWS 32768
#define NCTA 128
#define THR  256

typedef unsigned long long u64;
typedef unsigned int u32;

// ---------------- device scratch ----------------
__device__ float g_Wh4[(size_t)HID_ * G4];
__device__ float g_b4[G4];
__device__ float g_xproj[(size_t)MROWS * G4];                       // X@Wx + bias
// h stored directly in mma A-fragment layout (single fp16 image): [parity][ktile(64)][mtile(4)][lane(32)]
__device__ __align__(16) uint4 g_hfrag[2][64][4][32];
__device__ __align__(16) __nv_bfloat16 g_XH[(size_t)MROWS * XD];
__device__ __align__(16) __nv_bfloat16 g_XL[(size_t)MROWS * XD];
__device__ __align__(16) __nv_bfloat16 g_WXH[(size_t)G4 * XD];
__device__ __align__(16) __nv_bfloat16 g_WXL[(size_t)G4 * XD];
__device__ unsigned g_bar_cnt;
__device__ volatile unsigned g_bar_phase;

// ---------------- helpers ----------------
#define SW128(x) ((x) ^ (((x) >> 3) & 0x70))

__device__ __forceinline__ u32 smem_u32(const void* p) {
    u32 a; asm("{ .reg .u64 t; cvta.to.shared.u64 t, %1; cvt.u32.u64 %0, t; }" : "=r"(a) : "l"(p));
    return a;
}
__device__ __forceinline__ void ldsm4(u32& r0, u32& r1, u32& r2, u32& r3, u32 addr) {
    asm volatile("ldmatrix.sync.aligned.m8n8.x4.shared.b16 {%0,%1,%2,%3}, [%4];"
                 : "=r"(r0), "=r"(r1), "=r"(r2), "=r"(r3) : "r"(addr));
}
__device__ __forceinline__ void mma16816bf(float* c, u32 a0, u32 a1, u32 a2, u32 a3, u32 b0, u32 b1) {
    asm volatile("mma.sync.aligned.m16n8k16.row.col.f32.bf16.bf16.f32 "
                 "{%0,%1,%2,%3}, {%4,%5,%6,%7}, {%8,%9}, {%0,%1,%2,%3};"
                 : "+f"(c[0]), "+f"(c[1]), "+f"(c[2]), "+f"(c[3])
                 : "r"(a0), "r"(a1), "r"(a2), "r"(a3), "r"(b0), "r"(b1));
}
__device__ __forceinline__ void mma16816h(float* c, u32 a0, u32 a1, u32 a2, u32 a3, u32 b0, u32 b1) {
    asm volatile("mma.sync.aligned.m16n8k16.row.col.f32.f16.f16.f32 "
                 "{%0,%1,%2,%3}, {%4,%5,%6,%7}, {%8,%9}, {%0,%1,%2,%3};"
                 : "+f"(c[0]), "+f"(c[1]), "+f"(c[2]), "+f"(c[3])
                 : "r"(a0), "r"(a1), "r"(a2), "r"(a3), "r"(b0), "r"(b1));
}
__device__ __forceinline__ uint4 ldg_cg4(const uint4* p) {
    uint4 v;
    asm volatile("ld.global.cg.v4.u32 {%0,%1,%2,%3}, [%4];"
                 : "=r"(v.x), "=r"(v.y), "=r"(v.z), "=r"(v.w) : "l"(p));
    return v;
}
__device__ __forceinline__ void cp_async16(u32 dst, const void* src) {
    asm volatile("cp.async.cg.shared.global [%0], [%1], 16;" :: "r"(dst), "l"(src) : "memory");
}
__device__ __forceinline__ void cp_commit() { asm volatile("cp.async.commit_group;" ::: "memory"); }
template<int N> __device__ __forceinline__ void cp_wait() {
    asm volatile("cp.async.wait_group %0;" :: "n"(N) : "memory");
}
__device__ __forceinline__ float sigmoidf_(float x) { return 1.f / (1.f + __expf(-x)); }

__device__ __forceinline__ void bsplit(float v, __nv_bfloat16& hi, __nv_bfloat16& lo) {
    hi = __float2bfloat16(v);
    lo = __float2bfloat16(v - __bfloat162float(hi));
}

// ---------------- kernel 0: pack Wh gate-major + build bf16 images ----------------
__global__ void pack_kernel(const float* __restrict__ X,
                            const float* __restrict__ Wxi, const float* __restrict__ Wxf,
                            const float* __restrict__ Wxo, const float* __restrict__ Wxz,
                            const float* __restrict__ Whi, const float* __restrict__ Whf,
                            const float* __restrict__ Who, const float* __restrict__ Whz,
                            const float* __restrict__ bi,  const float* __restrict__ bf,
                            const float* __restrict__ bo,  const float* __restrict__ bz) {
    int tid0 = blockIdx.x * blockDim.x + threadIdx.x;
    int stride = gridDim.x * blockDim.x;
    for (int idx = tid0; idx < HID_ * G4; idx += stride) {
        int k = idx >> 12, col = idx & 4095, g = col >> 10, j = col & 1023;
        const float* W = (g == 0) ? Whi : (g == 1) ? Whf : (g == 2) ? Who : Whz;
        g_Wh4[idx] = W[k * HID_ + j];
    }
    for (int idx = tid0; idx < G4; idx += stride) {
        int g = idx >> 10, j = idx & 1023;
        const float* b = (g == 0) ? bi : (g == 1) ? bf : (g == 2) ? bo : bz;
        g_b4[idx] = b[j];
    }
    for (int idx = tid0; idx < MROWS * (XD / 4); idx += stride) {
        int m = idx >> 7, kq = (idx & 127) * 4;
        float4 v = *(const float4*)&X[(size_t)m * XD + kq];
        __nv_bfloat16 h[4], l[4];
        bsplit(v.x, h[0], l[0]); bsplit(v.y, h[1], l[1]);
        bsplit(v.z, h[2], l[2]); bsplit(v.w, h[3], l[3]);
        int mt = m >> 7, mloc = m & 127, ck = kq >> 6, kloc = kq & 63;
        size_t off = (size_t)(mt * 8 + ck) * 16384 + (size_t)((mloc >> 3) << 10)
                   + (size_t)SW128(((mloc & 7) << 7) + (kloc << 1));
        *(uint2*)((char*)g_XH + off) = *(uint2*)h;
        *(uint2*)((char*)g_XL + off) = *(uint2*)l;
    }
    for (int idx = tid0; idx < G4 * (XD / 4); idx += stride) {
        int n = idx >> 7, kq = (idx & 127) * 4;
        int g = n >> 10, j = n & 1023;
        const float* W = (g == 0) ? Wxi : (g == 1) ? Wxf : (g == 2) ? Wxo : Wxz;
        __nv_bfloat16 h[4], l[4];
#pragma unroll
        for (int i = 0; i < 4; i++) bsplit(W[(size_t)(kq + i) * HID_ + j], h[i], l[i]);
        int nt = n >> 7, nloc = n & 127, ck = kq >> 6, kloc = kq & 63;
        size_t off = (size_t)(nt * 8 + ck) * 16384 + (size_t)((nloc >> 3) << 10)
                   + (size_t)SW128(((nloc & 7) << 7) + (kloc << 1));
        *(uint2*)((char*)g_WXH + off) = *(uint2*)h;
        *(uint2*)((char*)g_WXL + off) = *(uint2*)l;
    }
}

// ---------------- kernel A: xproj (HMMA bf16 3-product, cp.async pipeline) ----------------
#define XP_SMEM 131072

__global__ __launch_bounds__(512) void xproj_kernel() {
    extern __shared__ __align__(1024) char xs[];
    u32 smem_base = smem_u32(xs);
    int tid = threadIdx.x;
    int lane = tid & 31, wid = tid >> 5;
    int mw = wid & 3, nw = (wid >> 2) & 3;
    int ntb = blockIdx.x, mtb = blockIdx.y;

    int r128 = tid >> 7, lane128 = tid & 127;

    auto issue = [&](int ck, int stage) {
        size_t xb = (size_t)(mtb * 8 + ck) * 16384 + (size_t)lane128 * 16;
        size_t wb = (size_t)(ntb * 8 + ck) * 16384 + (size_t)lane128 * 16;
        const char* src = (r128 == 0) ? (const char*)g_XH + xb
                        : (r128 == 1) ? (const char*)g_XL + xb
                        : (r128 == 2) ? (const char*)g_WXH + wb
                                      : (const char*)g_WXL + wb;
        u32 dst = smem_base + stage * 65536 + r128 * 16384 + lane128 * 16;
#pragma unroll
        for (int q = 0; q < 8; q++) cp_async16(dst + q * 2048, src + q * 2048);
        cp_commit();
    };

    float acc[2][4][4];
#pragma unroll
    for (int i = 0; i < 2; i++)
#pragma unroll
        for (int j = 0; j < 4; j++)
#pragma unroll
            for (int q = 0; q < 4; q++) acc[i][j][q] = 0.f;

    issue(0, 0);

    int kbA = (lane & 16) ? 8 : 0;
    int kbB = lane & 8;
    int ar0 = mw * 32 + (lane & 15);
    int br0 = nw * 32 + (lane & 7) + ((lane & 16) ? 8 : 0);

    for (int ck = 0; ck < 8; ck++) {
        if (ck < 7) { issue(ck + 1, (ck + 1) & 1); cp_wait<1>(); }
        else cp_wait<0>();
        __syncthreads();
        u32 sb = smem_base + (ck & 1) * 65536;
#pragma unroll
        for (int ks = 0; ks < 4; ks++) {
            int klA = ks * 16 + kbA;
            int klB = ks * 16 + kbB;
            u32 ah[2][4], al[2][4], bh[2][4], bl[2][4];
#pragma unroll
            for (int mt2 = 0; mt2 < 2; mt2++) {
                int ar = ar0 + mt2 * 16;
                u32 aoff = (u32)((ar >> 3) << 10) + (u32)SW128(((ar & 7) << 7) + (klA << 1));
                ldsm4(ah[mt2][0], ah[mt2][1], ah[mt2][2], ah[mt2][3], sb + aoff);
                ldsm4(al[mt2][0], al[mt2][1], al[mt2][2], al[mt2][3], sb + 16384 + aoff);
            }
#pragma unroll
            for (int bg = 0; bg < 2; bg++) {
                int br = br0 + bg * 16;
                u32 boff = (u32)((br >> 3) << 10) + (u32)SW128(((br & 7) << 7) + (klB << 1));
                ldsm4(bh[bg][0], bh[bg][1], bh[bg][2], bh[bg][3], sb + 32768 + boff);
                ldsm4(bl[bg][0], bl[bg][1], bl[bg][2], bl[bg][3], sb + 49152 + boff);
            }
#pragma unroll
            for (int mt2 = 0; mt2 < 2; mt2++)
#pragma unroll
                for (int bg = 0; bg < 2; bg++) {
                    float* c0 = acc[mt2][bg * 2];
                    float* c1 = acc[mt2][bg * 2 + 1];
                    mma16816bf(c0, ah[mt2][0], ah[mt2][1], ah[mt2][2], ah[mt2][3], bh[bg][0], bh[bg][1]);
                    mma16816bf(c0, ah[mt2][0], ah[mt2][1], ah[mt2][2], ah[mt2][3], bl[bg][0], bl[bg][1]);
                    mma16816bf(c0, al[mt2][0], al[mt2][1], al[mt2][2], al[mt2][3], bh[bg][0], bh[bg][1]);
                    mma16816bf(c1, ah[mt2][0], ah[mt2][1], ah[mt2][2], ah[mt2][3], bh[bg][2], bh[bg][3]);
                    mma16816bf(c1, ah[mt2][0], ah[mt2][1], ah[mt2][2], ah[mt2][3], bl[bg][2], bl[bg][3]);
                    mma16816bf(c1, al[mt2][0], al[mt2][1], al[mt2][2], al[mt2][3], bh[bg][2], bh[bg][3]);
                }
        }
        __syncthreads();
    }

    int rowb = mtb * 128 + mw * 32;
    int colb = ntb * 128 + nw * 32;
    float2 bias[4];
#pragma unroll
    for (int nc = 0; nc < 4; nc++) {
        int col = colb + (nc >> 1) * 16 + (nc & 1) * 8 + (lane & 3) * 2;
        bias[nc] = *(const float2*)&g_b4[col];
    }
#pragma unroll
    for (int mt2 = 0; mt2 < 2; mt2++) {
        int r0 = rowb + mt2 * 16 + (lane >> 2);
#pragma unroll
        for (int nc = 0; nc < 4; nc++) {
            int col = colb + (nc >> 1) * 16 + (nc & 1) * 8 + (lane & 3) * 2;
            *(float2*)&g_xproj[(size_t)r0 * G4 + col] =
                make_float2(acc[mt2][nc][0] + bias[nc].x, acc[mt2][nc][1] + bias[nc].y);
            *(float2*)&g_xproj[(size_t)(r0 + 8) * G4 + col] =
                make_float2(acc[mt2][nc][2] + bias[nc].x, acc[mt2][nc][3] + bias[nc].y);
        }
    }
}

// ---------------- kernel B: persistent HMMA recurrence (fp16 single-product) ----------------
// SMEM: [0,64K) Wh (fp16) | [64K, +34.8K) gsum
#define WHI_OFF   0
#define GSUM_OFF  65536
#define GROW      34
#define SMEM_BYTES (GSUM_OFF + 4 * BB * GROW * 4)

__device__ __forceinline__ void grid_sync(unsigned& phase) {
    __threadfence();
    __syncthreads();
    if (threadIdx.x == 0) {
        unsigned arrived = atomicAdd(&g_bar_cnt, 1u) + 1u;
        if (arrived == gridDim.x) {
            g_bar_cnt = 0;
            __threadfence();
            g_bar_phase = phase + 1u;
        } else {
            while (g_bar_phase == phase) { }
        }
        phase = phase + 1u;
        __threadfence();
    }
    __syncthreads();
}

__global__ __launch_bounds__(THR, 1) void lstm_kernel(float* __restrict__ out) {
    extern __shared__ __align__(1024) char sm[];
    u32 smem_base = smem_u32(sm);
    float* gsum = (float*)(sm + GSUM_OFF);
    int tid = threadIdx.x;
    int lane = tid & 31, wid = tid >> 5;
    int mt = wid & 1;                 // M-half
    int kq = wid >> 1;                // K-quarter
    int j0 = blockIdx.x * 8;

    // Wh slice -> single fp16 into SMEM atoms (8rows x 64cols, SW128)
    for (int idx = tid; idx < 32 * 1024; idx += THR) {
        int n = idx & 31, k = idx >> 5;
        int gc = (n >> 3) * 1024 + j0 + (n & 7);
        float wv = g_Wh4[(size_t)k * G4 + gc];
        __half hi = __float2half_rn(wv);
        u32 off = (u32)((n >> 3) + ((k >> 6) << 2)) * 1024u
                + (u32)SW128(((n & 7) << 7) + ((k & 63) << 1));
        *(__half*)(sm + WHI_OFF + off) = hi;
    }

    // ---- activation thread ownership + fragment write slot ----
    int ab = tid >> 2;                     // batch row 0..63
    int ajp = (tid & 3) * 2;               // j pair within CTA's 8 cols
    int rm = ab & 15;
    int w_mtile = ab >> 4;
    int w_ktile = blockIdx.x >> 1;         // (j0+ajp)>>4
    int w_L = (rm & 7) * 4 + (tid & 3);
    int w_r = ((rm >> 3) & 1) + ((blockIdx.x & 1) << 1);
    u32* wp = (u32*)&g_hfrag[0][w_ktile][w_mtile][w_L] + w_r;
    const size_t PAR_STRIDE_U32 = 64ull * 4 * 32 * 4;   // one parity in u32 units
    *wp = 0u;                              // zero parity-0 image
    float c0s = 0.f, c1s = 0.f;

    // mma B fragment address components
    int bcol_b = (lane & 7) + ((lane & 16) ? 8 : 0);
    int kbitB = lane & 8;

    unsigned phase = 0;
    if (tid == 0) phase = g_bar_phase;

    // xproj prefetch for step 0 (issued before the barrier: hides DRAM latency)
    const size_t xbase = ((size_t)ab * TT) * G4 + j0 + ajp;
    float2 xpv[4], xpn[4];
#pragma unroll
    for (int g = 0; g < 4; g++)
        xpv[g] = *(const float2*)&g_xproj[xbase + (size_t)g * 1024];

    grid_sync(phase);

    for (int t = 0; t < TT; t++) {
        int par = t & 1, npn = par ^ 1;
        const uint4* fH = &g_hfrag[par][0][0][0];

        float acc[2][4][4];
#pragma unroll
        for (int s = 0; s < 2; s++)
#pragma unroll
            for (int n = 0; n < 4; n++)
#pragma unroll
                for (int q = 0; q < 4; q++) acc[s][n][q] = 0.f;

        // prefetch chunk 0 A fragments
        uint4 aH[2][2], nH[2][2];   // [ks][sub]
#pragma unroll
        for (int ks = 0; ks < 2; ks++) {
            int kt = kq * 2 + ks;
#pragma unroll
            for (int sub = 0; sub < 2; sub++)
                aH[ks][sub] = ldg_cg4(fH + (kt * 4 + (mt * 2 + sub)) * 32 + lane);
        }

#pragma unroll 2
        for (int ck = 0; ck < 8; ck++) {
            if (ck < 7) {
#pragma unroll
                for (int ks = 0; ks < 2; ks++) {
                    int kt = (ck + 1) * 8 + kq * 2 + ks;
#pragma unroll
                    for (int sub = 0; sub < 2; sub++)
                        nH[ks][sub] = ldg_cg4(fH + (kt * 4 + (mt * 2 + sub)) * 32 + lane);
                }
            }
#pragma unroll
            for (int ks = 0; ks < 2; ks++) {
                int kB = ck * 128 + kq * 32 + ks * 16 + kbitB;
                u32 bh[2][4];
#pragma unroll
                for (int g16 = 0; g16 < 2; g16++) {
                    int bc = bcol_b + g16 * 16;
                    u32 boff = (u32)((bc >> 3) + ((kB >> 6) << 2)) * 1024u
                             + (u32)SW128(((bc & 7) << 7) + ((kB & 63) << 1));
                    ldsm4(bh[g16][0], bh[g16][1], bh[g16][2], bh[g16][3], smem_base + WHI_OFF + boff);
                }
#pragma unroll
                for (int sub = 0; sub < 2; sub++) {
                    uint4 ah = aH[ks][sub];
#pragma unroll
                    for (int g16 = 0; g16 < 2; g16++) {
                        mma16816h(acc[sub][g16 * 2],     ah.x, ah.y, ah.z, ah.w, bh[g16][0], bh[g16][1]);
                        mma16816h(acc[sub][g16 * 2 + 1], ah.x, ah.y, ah.z, ah.w, bh[g16][2], bh[g16][3]);
                    }
                }
            }
#pragma unroll
            for (int ks = 0; ks < 2; ks++)
#pragma unroll
                for (int sub = 0; sub < 2; sub++)
                    aH[ks][sub] = nH[ks][sub];
        }

        // fragment writeback: per-warp K-quarter region
        {
            float* gq = gsum + (size_t)kq * BB * GROW;
#pragma unroll
            for (int sub = 0; sub < 2; sub++) {
                int r0 = mt * 32 + sub * 16 + (lane >> 2);
#pragma unroll
                for (int n8 = 0; n8 < 4; n8++) {
                    int cb = n8 * 8 + (lane & 3) * 2;
                    *(float2*)&gq[r0 * GROW + cb]       = make_float2(acc[sub][n8][0], acc[sub][n8][1]);
                    *(float2*)&gq[(r0 + 8) * GROW + cb] = make_float2(acc[sub][n8][2], acc[sub][n8][3]);
                }
            }
        }
        __syncthreads();

        // activation: 2 cells per thread, sum 4 K-quarters
        {
            float gg[4][2];
#pragma unroll
            for (int g = 0; g < 4; g++) { gg[g][0] = xpv[g].x; gg[g][1] = xpv[g].y; }
#pragma unroll
            for (int q = 0; q < 4; q++) {
                const float* gq = gsum + (size_t)q * BB * GROW + ab * GROW + ajp;
#pragma unroll
                for (int g = 0; g < 4; g++) {
                    float2 v = *(const float2*)&gq[g * 8];
                    gg[g][0] += v.x; gg[g][1] += v.y;
                }
            }
            float i0 = sigmoidf_(gg[0][0]), f0 = sigmoidf_(gg[1][0]), o0 = sigmoidf_(gg[2][0]), z0 = tanhf(gg[3][0]);
            float i1 = sigmoidf_(gg[0][1]), f1 = sigmoidf_(gg[1][1]), o1 = sigmoidf_(gg[2][1]), z1 = tanhf(gg[3][1]);
            c0s = i0 * z0 + f0 * c0s;
            c1s = i1 * z1 + f1 * c1s;
            float hv0 = o0 * tanhf(c0s);
            float hv1 = o1 * tanhf(c1s);
            *(float2*)&out[((size_t)ab * TT + t) * HID_ + j0 + ajp] = make_float2(hv0, hv1);
            __half h0 = __float2half_rn(hv0);
            __half h1 = __float2half_rn(hv1);
            u32 hw = (u32)__half_as_ushort(h0) | ((u32)__half_as_ushort(h1) << 16);
            wp[(size_t)npn * PAR_STRIDE_U32] = hw;
        }

        // prefetch next-step xproj BEFORE the barrier (resolves during the wait)
        if (t + 1 < TT) {
#pragma unroll
            for (int g = 0; g < 4; g++)
                xpn[g] = *(const float2*)&g_xproj[xbase + (size_t)(t + 1) * G4 + (size_t)g * 1024];
            grid_sync(phase);
#pragma unroll
            for (int g = 0; g < 4; g++) xpv[g] = xpn[g];
        }
    }
}

// ---------------- launch ----------------
extern "C" void kernel_launch(void* const* d_in, const int* in_sizes, int n_in,
                              void* d_out, int out_size) {
    const float* X   = (const float*)d_in[0];
    const float* Whi = (const float*)d_in[1];
    const float* Wxi = (const float*)d_in[2];
    const float* bi  = (const float*)d_in[3];
    const float* Whf = (const float*)d_in[4];
    const float* Wxf = (const float*)d_in[5];
    const float* bf  = (const float*)d_in[6];
    const float* Who = (const float*)d_in[7];
    const float* Wxo = (const float*)d_in[8];
    const float* bo  = (const float*)d_in[9];
    const float* Whz = (const float*)d_in[10];
    const float* Wxz = (const float*)d_in[11];
    const float* bz  = (const float*)d_in[12];

    pack_kernel<<<2048, 256>>>(X, Wxi, Wxf, Wxo, Wxz, Whi, Whf, Who, Whz, bi, bf, bo, bz);

    cudaFuncSetAttribute(xproj_kernel, cudaFuncAttributeMaxDynamicSharedMemorySize, XP_SMEM);
    dim3 gA(32, 256);
    xproj_kernel<<<gA, 512, XP_SMEM>>>();

    cudaFuncSetAttribute(lstm_kernel, cudaFuncAttributeMaxDynamicSharedMemorySize, SMEM_BYTES);
    lstm_kernel<<<NCTA, THR, SMEM_BYTES>>>((float*)d_out);
}

// round 11
// speedup vs baseline: 3.0133x; 1.0547x over previous
#include <cuda_runtime.h>
#include <cuda_bf16.h>
#include <cuda_fp16.h>
#include <cstdint>
#include <cstddef>

#define XD   512
#define HID_ 1024
#define BB   64
#define TT   512
#define G4   4096
#define MROWS 32768
#define NCTA 128
#define THR  256

typedef unsigned long long u64;
typedef unsigned int u32;

// ---------------- device scratch ----------------
__device__ float g_Wh4[(size_t)HID_ * G4];
__device__ float g_b4[G4];
__device__ float g_xproj[(size_t)MROWS * G4];                       // X@Wx + bias
// h stored directly in mma A-fragment layout (single fp16 image): [parity][ktile(64)][mtile(4)][lane(32)]
__device__ __align__(16) uint4 g_hfrag[2][64][4][32];
__device__ __align__(16) __nv_bfloat16 g_XH[(size_t)MROWS * XD];
__device__ __align__(16) __nv_bfloat16 g_XL[(size_t)MROWS * XD];
__device__ __align__(16) __nv_bfloat16 g_WXH[(size_t)G4 * XD];
__device__ __align__(16) __nv_bfloat16 g_WXL[(size_t)G4 * XD];
__device__ unsigned g_bar_cnt;
__device__ volatile unsigned g_bar_phase;

// ---------------- helpers ----------------
#define SW128(x) ((x) ^ (((x) >> 3) & 0x70))

__device__ __forceinline__ u32 smem_u32(const void* p) {
    u32 a; asm("{ .reg .u64 t; cvta.to.shared.u64 t, %1; cvt.u32.u64 %0, t; }" : "=r"(a) : "l"(p));
    return a;
}
__device__ __forceinline__ void ldsm4(u32& r0, u32& r1, u32& r2, u32& r3, u32 addr) {
    asm volatile("ldmatrix.sync.aligned.m8n8.x4.shared.b16 {%0,%1,%2,%3}, [%4];"
                 : "=r"(r0), "=r"(r1), "=r"(r2), "=r"(r3) : "r"(addr));
}
__device__ __forceinline__ void mma16816bf(float* c, u32 a0, u32 a1, u32 a2, u32 a3, u32 b0, u32 b1) {
    asm volatile("mma.sync.aligned.m16n8k16.row.col.f32.bf16.bf16.f32 "
                 "{%0,%1,%2,%3}, {%4,%5,%6,%7}, {%8,%9}, {%0,%1,%2,%3};"
                 : "+f"(c[0]), "+f"(c[1]), "+f"(c[2]), "+f"(c[3])
                 : "r"(a0), "r"(a1), "r"(a2), "r"(a3), "r"(b0), "r"(b1));
}
__device__ __forceinline__ void mma16816h(float* c, u32 a0, u32 a1, u32 a2, u32 a3, u32 b0, u32 b1) {
    asm volatile("mma.sync.aligned.m16n8k16.row.col.f32.f16.f16.f32 "
                 "{%0,%1,%2,%3}, {%4,%5,%6,%7}, {%8,%9}, {%0,%1,%2,%3};"
                 : "+f"(c[0]), "+f"(c[1]), "+f"(c[2]), "+f"(c[3])
                 : "r"(a0), "r"(a1), "r"(a2), "r"(a3), "r"(b0), "r"(b1));
}
__device__ __forceinline__ uint4 ldg_cg4(const uint4* p) {
    uint4 v;
    asm volatile("ld.global.cg.v4.u32 {%0,%1,%2,%3}, [%4];"
                 : "=r"(v.x), "=r"(v.y), "=r"(v.z), "=r"(v.w) : "l"(p));
    return v;
}
__device__ __forceinline__ void cp_async16(u32 dst, const void* src) {
    asm volatile("cp.async.cg.shared.global [%0], [%1], 16;" :: "r"(dst), "l"(src) : "memory");
}
__device__ __forceinline__ void cp_commit() { asm volatile("cp.async.commit_group;" ::: "memory"); }
template<int N> __device__ __forceinline__ void cp_wait() {
    asm volatile("cp.async.wait_group %0;" :: "n"(N) : "memory");
}
__device__ __forceinline__ float sigmoidf_(float x) { return 1.f / (1.f + __expf(-x)); }

__device__ __forceinline__ void bsplit(float v, __nv_bfloat16& hi, __nv_bfloat16& lo) {
    hi = __float2bfloat16(v);
    lo = __float2bfloat16(v - __bfloat162float(hi));
}

// ---------------- kernel 0: pack Wh gate-major + build bf16 images ----------------
__global__ void pack_kernel(const float* __restrict__ X,
                            const float* __restrict__ Wxi, const float* __restrict__ Wxf,
                            const float* __restrict__ Wxo, const float* __restrict__ Wxz,
                            const float* __restrict__ Whi, const float* __restrict__ Whf,
                            const float* __restrict__ Who, const float* __restrict__ Whz,
                            const float* __restrict__ bi,  const float* __restrict__ bf,
                            const float* __restrict__ bo,  const float* __restrict__ bz) {
    int tid0 = blockIdx.x * blockDim.x + threadIdx.x;
    int stride = gridDim.x * blockDim.x;
    for (int idx = tid0; idx < HID_ * G4; idx += stride) {
        int k = idx >> 12, col = idx & 4095, g = col >> 10, j = col & 1023;
        const float* W = (g == 0) ? Whi : (g == 1) ? Whf : (g == 2) ? Who : Whz;
        g_Wh4[idx] = W[k * HID_ + j];
    }
    for (int idx = tid0; idx < G4; idx += stride) {
        int g = idx >> 10, j = idx & 1023;
        const float* b = (g == 0) ? bi : (g == 1) ? bf : (g == 2) ? bo : bz;
        g_b4[idx] = b[j];
    }
    for (int idx = tid0; idx < MROWS * (XD / 4); idx += stride) {
        int m = idx >> 7, kq = (idx & 127) * 4;
        float4 v = *(const float4*)&X[(size_t)m * XD + kq];
        __nv_bfloat16 h[4], l[4];
        bsplit(v.x, h[0], l[0]); bsplit(v.y, h[1], l[1]);
        bsplit(v.z, h[2], l[2]); bsplit(v.w, h[3], l[3]);
        int mt = m >> 7, mloc = m & 127, ck = kq >> 6, kloc = kq & 63;
        size_t off = (size_t)(mt * 8 + ck) * 16384 + (size_t)((mloc >> 3) << 10)
                   + (size_t)SW128(((mloc & 7) << 7) + (kloc << 1));
        *(uint2*)((char*)g_XH + off) = *(uint2*)h;
        *(uint2*)((char*)g_XL + off) = *(uint2*)l;
    }
    for (int idx = tid0; idx < G4 * (XD / 4); idx += stride) {
        int n = idx >> 7, kq = (idx & 127) * 4;
        int g = n >> 10, j = n & 1023;
        const float* W = (g == 0) ? Wxi : (g == 1) ? Wxf : (g == 2) ? Wxo : Wxz;
        __nv_bfloat16 h[4], l[4];
#pragma unroll
        for (int i = 0; i < 4; i++) bsplit(W[(size_t)(kq + i) * HID_ + j], h[i], l[i]);
        int nt = n >> 7, nloc = n & 127, ck = kq >> 6, kloc = kq & 63;
        size_t off = (size_t)(nt * 8 + ck) * 16384 + (size_t)((nloc >> 3) << 10)
                   + (size_t)SW128(((nloc & 7) << 7) + (kloc << 1));
        *(uint2*)((char*)g_WXH + off) = *(uint2*)h;
        *(uint2*)((char*)g_WXL + off) = *(uint2*)l;
    }
}

// ---------------- kernel A: xproj (HMMA bf16 3-product, cp.async pipeline) ----------------
#define XP_SMEM 131072

__global__ __launch_bounds__(512) void xproj_kernel() {
    extern __shared__ __align__(1024) char xs[];
    u32 smem_base = smem_u32(xs);
    int tid = threadIdx.x;
    int lane = tid & 31, wid = tid >> 5;
    int mw = wid & 3, nw = (wid >> 2) & 3;
    int ntb = blockIdx.x, mtb = blockIdx.y;

    int r128 = tid >> 7, lane128 = tid & 127;

    auto issue = [&](int ck, int stage) {
        size_t xb = (size_t)(mtb * 8 + ck) * 16384 + (size_t)lane128 * 16;
        size_t wb = (size_t)(ntb * 8 + ck) * 16384 + (size_t)lane128 * 16;
        const char* src = (r128 == 0) ? (const char*)g_XH + xb
                        : (r128 == 1) ? (const char*)g_XL + xb
                        : (r128 == 2) ? (const char*)g_WXH + wb
                                      : (const char*)g_WXL + wb;
        u32 dst = smem_base + stage * 65536 + r128 * 16384 + lane128 * 16;
#pragma unroll
        for (int q = 0; q < 8; q++) cp_async16(dst + q * 2048, src + q * 2048);
        cp_commit();
    };

    float acc[2][4][4];
#pragma unroll
    for (int i = 0; i < 2; i++)
#pragma unroll
        for (int j = 0; j < 4; j++)
#pragma unroll
            for (int q = 0; q < 4; q++) acc[i][j][q] = 0.f;

    issue(0, 0);

    int kbA = (lane & 16) ? 8 : 0;
    int kbB = lane & 8;
    int ar0 = mw * 32 + (lane & 15);
    int br0 = nw * 32 + (lane & 7) + ((lane & 16) ? 8 : 0);

    for (int ck = 0; ck < 8; ck++) {
        if (ck < 7) { issue(ck + 1, (ck + 1) & 1); cp_wait<1>(); }
        else cp_wait<0>();
        __syncthreads();
        u32 sb = smem_base + (ck & 1) * 65536;
#pragma unroll
        for (int ks = 0; ks < 4; ks++) {
            int klA = ks * 16 + kbA;
            int klB = ks * 16 + kbB;
            u32 ah[2][4], al[2][4], bh[2][4], bl[2][4];
#pragma unroll
            for (int mt2 = 0; mt2 < 2; mt2++) {
                int ar = ar0 + mt2 * 16;
                u32 aoff = (u32)((ar >> 3) << 10) + (u32)SW128(((ar & 7) << 7) + (klA << 1));
                ldsm4(ah[mt2][0], ah[mt2][1], ah[mt2][2], ah[mt2][3], sb + aoff);
                ldsm4(al[mt2][0], al[mt2][1], al[mt2][2], al[mt2][3], sb + 16384 + aoff);
            }
#pragma unroll
            for (int bg = 0; bg < 2; bg++) {
                int br = br0 + bg * 16;
                u32 boff = (u32)((br >> 3) << 10) + (u32)SW128(((br & 7) << 7) + (klB << 1));
                ldsm4(bh[bg][0], bh[bg][1], bh[bg][2], bh[bg][3], sb + 32768 + boff);
                ldsm4(bl[bg][0], bl[bg][1], bl[bg][2], bl[bg][3], sb + 49152 + boff);
            }
#pragma unroll
            for (int mt2 = 0; mt2 < 2; mt2++)
#pragma unroll
                for (int bg = 0; bg < 2; bg++) {
                    float* c0 = acc[mt2][bg * 2];
                    float* c1 = acc[mt2][bg * 2 + 1];
                    mma16816bf(c0, ah[mt2][0], ah[mt2][1], ah[mt2][2], ah[mt2][3], bh[bg][0], bh[bg][1]);
                    mma16816bf(c0, ah[mt2][0], ah[mt2][1], ah[mt2][2], ah[mt2][3], bl[bg][0], bl[bg][1]);
                    mma16816bf(c0, al[mt2][0], al[mt2][1], al[mt2][2], al[mt2][3], bh[bg][0], bh[bg][1]);
                    mma16816bf(c1, ah[mt2][0], ah[mt2][1], ah[mt2][2], ah[mt2][3], bh[bg][2], bh[bg][3]);
                    mma16816bf(c1, ah[mt2][0], ah[mt2][1], ah[mt2][2], ah[mt2][3], bl[bg][2], bl[bg][3]);
                    mma16816bf(c1, al[mt2][0], al[mt2][1], al[mt2][2], al[mt2][3], bh[bg][2], bh[bg][3]);
                }
        }
        __syncthreads();
    }

    int rowb = mtb * 128 + mw * 32;
    int colb = ntb * 128 + nw * 32;
    float2 bias[4];
#pragma unroll
    for (int nc = 0; nc < 4; nc++) {
        int col = colb + (nc >> 1) * 16 + (nc & 1) * 8 + (lane & 3) * 2;
        bias[nc] = *(const float2*)&g_b4[col];
    }
#pragma unroll
    for (int mt2 = 0; mt2 < 2; mt2++) {
        int r0 = rowb + mt2 * 16 + (lane >> 2);
#pragma unroll
        for (int nc = 0; nc < 4; nc++) {
            int col = colb + (nc >> 1) * 16 + (nc & 1) * 8 + (lane & 3) * 2;
            *(float2*)&g_xproj[(size_t)r0 * G4 + col] =
                make_float2(acc[mt2][nc][0] + bias[nc].x, acc[mt2][nc][1] + bias[nc].y);
            *(float2*)&g_xproj[(size_t)(r0 + 8) * G4 + col] =
                make_float2(acc[mt2][nc][2] + bias[nc].x, acc[mt2][nc][3] + bias[nc].y);
        }
    }
}

// ---------------- kernel B: persistent HMMA recurrence (fp16 single-product, deep prefetch) ----------------
// SMEM: [0,64K) Wh (fp16) | [64K, +34.8K) gsum
#define WHI_OFF   0
#define GSUM_OFF  65536
#define GROW      34
#define SMEM_BYTES (GSUM_OFF + 4 * BB * GROW * 4)

__device__ __forceinline__ void grid_sync(unsigned& phase) {
    __syncthreads();
    if (threadIdx.x == 0) {
        __threadfence();     // cumulative fence publishes the whole CTA's prior writes
        unsigned arrived = atomicAdd(&g_bar_cnt, 1u) + 1u;
        if (arrived == gridDim.x) {
            g_bar_cnt = 0;
            __threadfence();
            g_bar_phase = phase + 1u;
        } else {
            while (g_bar_phase == phase) { }
        }
        phase = phase + 1u;
        __threadfence();
    }
    __syncthreads();
}

__global__ __launch_bounds__(THR, 1) void lstm_kernel(float* __restrict__ out) {
    extern __shared__ __align__(1024) char sm[];
    u32 smem_base = smem_u32(sm);
    float* gsum = (float*)(sm + GSUM_OFF);
    int tid = threadIdx.x;
    int lane = tid & 31, wid = tid >> 5;
    int mt = wid & 1;                 // M-half
    int kq = wid >> 1;                // K-quarter
    int j0 = blockIdx.x * 8;

    // Wh slice -> single fp16 into SMEM atoms (8rows x 64cols, SW128)
    for (int idx = tid; idx < 32 * 1024; idx += THR) {
        int n = idx & 31, k = idx >> 5;
        int gc = (n >> 3) * 1024 + j0 + (n & 7);
        float wv = g_Wh4[(size_t)k * G4 + gc];
        __half hi = __float2half_rn(wv);
        u32 off = (u32)((n >> 3) + ((k >> 6) << 2)) * 1024u
                + (u32)SW128(((n & 7) << 7) + ((k & 63) << 1));
        *(__half*)(sm + WHI_OFF + off) = hi;
    }

    // ---- activation thread ownership + fragment write slot ----
    int ab = tid >> 2;                     // batch row 0..63
    int ajp = (tid & 3) * 2;               // j pair within CTA's 8 cols
    int rm = ab & 15;
    int w_mtile = ab >> 4;
    int w_ktile = blockIdx.x >> 1;         // (j0+ajp)>>4
    int w_L = (rm & 7) * 4 + (tid & 3);
    int w_r = ((rm >> 3) & 1) + ((blockIdx.x & 1) << 1);
    u32* wp = (u32*)&g_hfrag[0][w_ktile][w_mtile][w_L] + w_r;
    const size_t PAR_STRIDE_U32 = 64ull * 4 * 32 * 4;   // one parity in u32 units
    *wp = 0u;                              // zero parity-0 image
    float c0s = 0.f, c1s = 0.f;

    // mma B fragment address components
    int bcol_b = (lane & 7) + ((lane & 16) ? 8 : 0);
    int kbitB = lane & 8;

    unsigned phase = 0;
    if (tid == 0) phase = g_bar_phase;

    // xproj prefetch for step 0 (issued before the barrier: hides DRAM latency)
    const size_t xbase = ((size_t)ab * TT) * G4 + j0 + ajp;
    float2 xpv[4], xpn[4];
#pragma unroll
    for (int g = 0; g < 4; g++)
        xpv[g] = *(const float2*)&g_xproj[xbase + (size_t)g * 1024];

    grid_sync(phase);

    for (int t = 0; t < TT; t++) {
        int par = t & 1, npn = par ^ 1;
        const uint4* fH = &g_hfrag[par][0][0][0];

        float acc[2][4][4];
#pragma unroll
        for (int s = 0; s < 2; s++)
#pragma unroll
            for (int n = 0; n < 4; n++)
#pragma unroll
                for (int q = 0; q < 4; q++) acc[s][n][q] = 0.f;

        // rotating 3-slot A-fragment buffer, prefetch depth 2 (fully static indices)
        uint4 A[3][2][2];
#pragma unroll
        for (int pf = 0; pf < 2; pf++)
#pragma unroll
            for (int ks = 0; ks < 2; ks++)
#pragma unroll
                for (int sub = 0; sub < 2; sub++)
                    A[pf][ks][sub] = ldg_cg4(fH + ((pf * 8 + kq * 2 + ks) * 4 + (mt * 2 + sub)) * 32 + lane);

#pragma unroll
        for (int ck = 0; ck < 8; ck++) {
            if (ck + 2 < 8) {
#pragma unroll
                for (int ks = 0; ks < 2; ks++)
#pragma unroll
                    for (int sub = 0; sub < 2; sub++)
                        A[(ck + 2) % 3][ks][sub] =
                            ldg_cg4(fH + (((ck + 2) * 8 + kq * 2 + ks) * 4 + (mt * 2 + sub)) * 32 + lane);
            }
#pragma unroll
            for (int ks = 0; ks < 2; ks++) {
                int kB = ck * 128 + kq * 32 + ks * 16 + kbitB;
                u32 bh[2][4];
#pragma unroll
                for (int g16 = 0; g16 < 2; g16++) {
                    int bc = bcol_b + g16 * 16;
                    u32 boff = (u32)((bc >> 3) + ((kB >> 6) << 2)) * 1024u
                             + (u32)SW128(((bc & 7) << 7) + ((kB & 63) << 1));
                    ldsm4(bh[g16][0], bh[g16][1], bh[g16][2], bh[g16][3], smem_base + WHI_OFF + boff);
                }
#pragma unroll
                for (int sub = 0; sub < 2; sub++) {
                    uint4 ah = A[ck % 3][ks][sub];
#pragma unroll
                    for (int g16 = 0; g16 < 2; g16++) {
                        mma16816h(acc[sub][g16 * 2],     ah.x, ah.y, ah.z, ah.w, bh[g16][0], bh[g16][1]);
                        mma16816h(acc[sub][g16 * 2 + 1], ah.x, ah.y, ah.z, ah.w, bh[g16][2], bh[g16][3]);
                    }
                }
            }
        }

        // fragment writeback: per-warp K-quarter region
        {
            float* gq = gsum + (size_t)kq * BB * GROW;
#pragma unroll
            for (int sub = 0; sub < 2; sub++) {
                int r0 = mt * 32 + sub * 16 + (lane >> 2);
#pragma unroll
                for (int n8 = 0; n8 < 4; n8++) {
                    int cb = n8 * 8 + (lane & 3) * 2;
                    *(float2*)&gq[r0 * GROW + cb]       = make_float2(acc[sub][n8][0], acc[sub][n8][1]);
                    *(float2*)&gq[(r0 + 8) * GROW + cb] = make_float2(acc[sub][n8][2], acc[sub][n8][3]);
                }
            }
        }
        __syncthreads();

        // activation: 2 cells per thread, sum 4 K-quarters
        {
            float gg[4][2];
#pragma unroll
            for (int g = 0; g < 4; g++) { gg[g][0] = xpv[g].x; gg[g][1] = xpv[g].y; }
#pragma unroll
            for (int q = 0; q < 4; q++) {
                const float* gq = gsum + (size_t)q * BB * GROW + ab * GROW + ajp;
#pragma unroll
                for (int g = 0; g < 4; g++) {
                    float2 v = *(const float2*)&gq[g * 8];
                    gg[g][0] += v.x; gg[g][1] += v.y;
                }
            }
            float i0 = sigmoidf_(gg[0][0]), f0 = sigmoidf_(gg[1][0]), o0 = sigmoidf_(gg[2][0]), z0 = tanhf(gg[3][0]);
            float i1 = sigmoidf_(gg[0][1]), f1 = sigmoidf_(gg[1][1]), o1 = sigmoidf_(gg[2][1]), z1 = tanhf(gg[3][1]);
            c0s = i0 * z0 + f0 * c0s;
            c1s = i1 * z1 + f1 * c1s;
            float hv0 = o0 * tanhf(c0s);
            float hv1 = o1 * tanhf(c1s);
            *(float2*)&out[((size_t)ab * TT + t) * HID_ + j0 + ajp] = make_float2(hv0, hv1);
            __half h0 = __float2half_rn(hv0);
            __half h1 = __float2half_rn(hv1);
            u32 hw = (u32)__half_as_ushort(h0) | ((u32)__half_as_ushort(h1) << 16);
            wp[(size_t)npn * PAR_STRIDE_U32] = hw;
        }

        // prefetch next-step xproj BEFORE the barrier (resolves during the wait)
        if (t + 1 < TT) {
#pragma unroll
            for (int g = 0; g < 4; g++)
                xpn[g] = *(const float2*)&g_xproj[xbase + (size_t)(t + 1) * G4 + (size_t)g * 1024];
            grid_sync(phase);
#pragma unroll
            for (int g = 0; g < 4; g++) xpv[g] = xpn[g];
        }
    }
}

// ---------------- launch ----------------
extern "C" void kernel_launch(void* const* d_in, const int* in_sizes, int n_in,
                              void* d_out, int out_size) {
    const float* X   = (const float*)d_in[0];
    const float* Whi = (const float*)d_in[1];
    const float* Wxi = (const float*)d_in[2];
    const float* bi  = (const float*)d_in[3];
    const float* Whf = (const float*)d_in[4];
    const float* Wxf = (const float*)d_in[5];
    const float* bf  = (const float*)d_in[6];
    const float* Who = (const float*)d_in[7];
    const float* Wxo = (const float*)d_in[8];
    const float* bo  = (const float*)d_in[9];
    const float* Whz = (const float*)d_in[10];
    const float* Wxz = (const float*)d_in[11];
    const float* bz  = (const float*)d_in[12];

    pack_kernel<<<2048, 256>>>(X, Wxi, Wxf, Wxo, Wxz, Whi, Whf, Who, Whz, bi, bf, bo, bz);

    cudaFuncSetAttribute(xproj_kernel, cudaFuncAttributeMaxDynamicSharedMemorySize, XP_SMEM);
    dim3 gA(32, 256);
    xproj_kernel<<<gA, 512, XP_SMEM>>>();

    cudaFuncSetAttribute(lstm_kernel, cudaFuncAttributeMaxDynamicSharedMemorySize, SMEM_BYTES);
    lstm_kernel<<<NCTA, THR, SMEM_BYTES>>>((float*)d_out);
}